// round 6
// baseline (speedup 1.0000x reference)
#include <cuda_runtime.h>
#include <math.h>

#define BB 4
#define NN 32
#define DD 128
#define HH 8
#define NCC 27
#define DFF 512
#define LL (NCC*NN)        // 864
#define NR (BB*NN)         // 128 token rows

// ---------------- scratch (static device globals; no allocation) -------------
__device__ __align__(16) float g_xb[NR*DD];                 // x + bp
__device__ float g_mxb[NR], g_ssxb[NR];                     // row mean / sumsq of xb
__device__ float g_XW[NR*3];                                // xb @ Wp^T
__device__ __align__(16) float g_Xq[NR*DD], g_Xk[NR*DD], g_Xv[NR*DD];  // (xb*g1)@W
__device__ float g_Mk[3*DD], g_Mv[3*DD];                    // Wp*diag(g1)*W
__device__ float g_uq[DD], g_uk[DD], g_uv[DD];              // g1@W
__device__ float g_cq[DD], g_ck[DD], g_cv[DD];              // b1@W + bias
__device__ float g_G[9], g_rs[3];                           // Wp Wp^T (3x3), Wp row sums
__device__ __align__(16) float g_y[NR*DD], g_hn2[NR*DD];

__inline__ __device__ float warpSum(float v){
    #pragma unroll
    for (int o = 16; o; o >>= 1) v += __shfl_down_sync(0xffffffffu, v, o);
    return v;
}

// ================= K1: precomputes (55 blocks x 256) ==========================
// blocks 0..47 : tiled GEMM  (xb*g1)[128x128] @ [Wq|Wk|Wv][128x384]
// blocks 48..51: per-row stats (mxb, ssxb, XW) + g_xb, 32 rows each
// block 52     : Mk, Mv = (Wp*diag(g1)) @ {Wk,Wv}
// block 53     : u = g1@W, c = b1@W + bias, for q/k/v
// block 54     : G = Wp Wp^T, rs = Wp row sums
__global__ void __launch_bounds__(256)
k_pre(const float* __restrict__ x,
      const float* __restrict__ Wp, const float* __restrict__ bp,
      const float* __restrict__ Wq, const float* __restrict__ bq,
      const float* __restrict__ Wk, const float* __restrict__ bk,
      const float* __restrict__ Wv, const float* __restrict__ bv,
      const float* __restrict__ g1, const float* __restrict__ b1)
{
    __shared__ __align__(16) float As[32][129];   // 16.5 KB
    __shared__ __align__(16) float Bs[128][32];   // 16 KB
    int bid = blockIdx.x, tid = threadIdx.x;

    if (bid < 48){
        int rt = bid / 12, ct = bid % 12;
        int m = ct >> 2, j0 = (ct & 3) * 32;
        const float* W = (m==0) ? Wq : ((m==1) ? Wk : Wv);
        float* O       = (m==0) ? g_Xq : ((m==1) ? g_Xk : g_Xv);
        int r0 = rt * 32;

        for (int idx = tid; idx < 4096; idx += 256){
            int r = idx >> 7, k = idx & 127;
            As[r][k] = (x[(r0+r)*DD + k] + bp[k]) * g1[k];
        }
        for (int idx = tid; idx < 4096; idx += 256){
            int k = idx >> 5, j = idx & 31;
            Bs[k][j] = W[k*DD + j0 + j];
        }
        __syncthreads();

        int r = tid >> 3, j4 = (tid & 7) * 4;
        float a0=0.f, a1=0.f, a2=0.f, a3=0.f;
        #pragma unroll 4
        for (int k = 0; k < 128; k++){
            float a = As[r][k];
            float4 w = *(const float4*)&Bs[k][j4];
            a0 = fmaf(a, w.x, a0); a1 = fmaf(a, w.y, a1);
            a2 = fmaf(a, w.z, a2); a3 = fmaf(a, w.w, a3);
        }
        float4 o; o.x=a0; o.y=a1; o.z=a2; o.w=a3;
        *(float4*)&O[(r0+r)*DD + j0 + j4] = o;
    }
    else if (bid < 52){
        // stats: warp w handles rows r0+w, r0+w+8, ... (4 rows)
        int r0 = (bid-48)*32;
        int w = tid >> 5, lane = tid & 31;
        for (int rr = w; rr < 32; rr += 8){
            int row = r0 + rr;
            float4 xv = *(const float4*)&x[row*DD + lane*4];
            float4 b4 = *(const float4*)&bp[lane*4];
            float v0 = xv.x+b4.x, v1 = xv.y+b4.y, v2 = xv.z+b4.z, v3 = xv.w+b4.w;
            float4 ov; ov.x=v0; ov.y=v1; ov.z=v2; ov.w=v3;
            *(float4*)&g_xb[row*DD + lane*4] = ov;
            float4 w0 = *(const float4*)&Wp[lane*4];
            float4 w1 = *(const float4*)&Wp[DD + lane*4];
            float4 w2 = *(const float4*)&Wp[2*DD + lane*4];
            float s  = v0+v1+v2+v3;
            float ss = v0*v0+v1*v1+v2*v2+v3*v3;
            float p0 = v0*w0.x+v1*w0.y+v2*w0.z+v3*w0.w;
            float p1 = v0*w1.x+v1*w1.y+v2*w1.z+v3*w1.w;
            float p2 = v0*w2.x+v1*w2.y+v2*w2.z+v3*w2.w;
            s  = warpSum(s);  ss = warpSum(ss);
            p0 = warpSum(p0); p1 = warpSum(p1); p2 = warpSum(p2);
            if (lane == 0){
                g_mxb[row]  = s * (1.0f/128.0f);
                g_ssxb[row] = ss;
                g_XW[row*3+0] = p0; g_XW[row*3+1] = p1; g_XW[row*3+2] = p2;
            }
        }
    }
    else if (bid == 52){
        // Mk/Mv: thread j computes col j of 3 rows; coalesced W reads
        float (*wpg)[129] = (float(*)[129])As;
        for (int idx = tid; idx < 384; idx += 256)
            wpg[idx>>7][idx&127] = Wp[idx] * g1[idx & 127];
        __syncthreads();
        int j = tid & 127;
        const float* W = (tid < 128) ? Wk : Wv;
        float* M       = (tid < 128) ? g_Mk : g_Mv;
        float m0=0.f, m1=0.f, m2=0.f;
        #pragma unroll 8
        for (int k = 0; k < 128; k++){
            float w = W[k*DD + j];
            m0 = fmaf(wpg[0][k], w, m0);
            m1 = fmaf(wpg[1][k], w, m1);
            m2 = fmaf(wpg[2][k], w, m2);
        }
        M[j] = m0; M[DD+j] = m1; M[2*DD+j] = m2;
    }
    else if (bid == 53){
        // u/c for q,k,v: coalesced W reads, thread j, half selects g1/b1
        float (*gb)[129] = (float(*)[129])As;
        if (tid < 128){ gb[0][tid] = g1[tid]; gb[1][tid] = b1[tid]; }
        __syncthreads();
        int j = tid & 127, half = tid >> 7;
        #pragma unroll 1
        for (int m = 0; m < 3; m++){
            const float* W = (m==0) ? Wq : ((m==1) ? Wk : Wv);
            float acc = 0.0f;
            #pragma unroll 8
            for (int k = 0; k < 128; k++) acc = fmaf(gb[half][k], W[k*DD + j], acc);
            if (half == 0){
                ((m==0) ? g_uq : ((m==1) ? g_uk : g_uv))[j] = acc;
            } else {
                const float* bias = (m==0) ? bq : ((m==1) ? bk : bv);
                ((m==0) ? g_cq : ((m==1) ? g_ck : g_cv))[j] = acc + bias[j];
            }
        }
    }
    else {
        if (tid < 9){
            int a = tid/3, c = tid%3;
            float acc = 0.0f;
            #pragma unroll 8
            for (int k = 0; k < 128; k++) acc = fmaf(Wp[a*DD+k], Wp[c*DD+k], acc);
            g_G[tid] = acc;
        } else if (tid < 12){
            int a = tid - 9;
            float acc = 0.0f;
            #pragma unroll 8
            for (int k = 0; k < 128; k++) acc += Wp[a*DD+k];
            g_rs[a] = acc;
        }
    }
}

// ================= K2: attention per (b,i) — factored form ====================
__global__ void __launch_bounds__(256)
k_attn2(const float* __restrict__ coords, const int* __restrict__ mask,
        const float* __restrict__ Wo, const float* __restrict__ bo,
        const float* __restrict__ uqp, const float* __restrict__ cqp,
        const float* __restrict__ g2, const float* __restrict__ b2)
{
    __shared__ float s_sc[HH][LL];        // 27.6 KB
    __shared__ float s_mu[LL], s_rstd[LL];
    __shared__ float s_q[128];
    __shared__ float s_QXk[HH][32];
    __shared__ float s_qMk[HH][4], s_quk[HH], s_qck[HH];
    __shared__ float s_A[HH][32], s_B[HH][4], s_G8[HH];
    __shared__ float s_mxb[32], s_ssxb[32], s_XW[32][3];
    __shared__ float s_atts[128], s_op[2][128];
    __shared__ float rsm[4][2], stat[2];
    __shared__ int   mk[32];

    int bid = blockIdx.x, tid = threadIdx.x;
    int b = bid >> 5, i = bid & 31;
    const float* cb = coords + b*LL*3;

    if (tid < 32){
        mk[tid]     = mask[b*32 + tid];
        s_mxb[tid]  = g_mxb[b*32 + tid];
        s_ssxb[tid] = g_ssxb[b*32 + tid];
    }
    for (int t = tid; t < 96; t += 256) s_XW[t/3][t%3] = g_XW[b*96 + t];

    float mu_i = g_mxb[bid];
    float rstd_i = rsqrtf(g_ssxb[bid]*(1.0f/128.0f) - mu_i*mu_i + 1e-5f);
    if (tid < 128)
        s_q[tid] = rstd_i*g_Xq[bid*DD + tid] - rstd_i*mu_i*uqp[tid] + cqp[tid];
    __syncthreads();

    {
        int h = tid >> 5, n = tid & 31;
        float acc = 0.0f;
        #pragma unroll
        for (int j = 0; j < 16; j++)
            acc = fmaf(s_q[h*16+j], g_Xk[(b*32+n)*DD + h*16 + j], acc);
        s_QXk[h][n] = acc;
    }
    if (tid < 24){
        int h = tid/3, a = tid%3;
        float acc = 0.0f;
        #pragma unroll
        for (int j = 0; j < 16; j++) acc = fmaf(s_q[h*16+j], g_Mk[a*DD + h*16 + j], acc);
        s_qMk[h][a] = acc;
    } else if (tid < 32){
        int h = tid - 24;
        float acc = 0.0f;
        #pragma unroll
        for (int j = 0; j < 16; j++) acc = fmaf(s_q[h*16+j], g_uk[h*16+j], acc);
        s_quk[h] = acc;
    } else if (tid < 40){
        int h = tid - 32;
        float acc = 0.0f;
        #pragma unroll
        for (int j = 0; j < 16; j++) acc = fmaf(s_q[h*16+j], g_ck[h*16+j], acc);
        s_qck[h] = acc;
    }
    __syncthreads();

    float Gr[9], rr[3];
    #pragma unroll
    for (int a = 0; a < 9; a++) Gr[a] = g_G[a];
    #pragma unroll
    for (int a = 0; a < 3; a++) rr[a] = g_rs[a] * (1.0f/128.0f);

    for (int l = tid; l < LL; l += 256){
        int c = l >> 5, n = l & 31;
        int lb = l*3, ib = (c*32 + i)*3;
        float d0 = cb[lb]   - cb[ib];
        float d1 = cb[lb+1] - cb[ib+1];
        float d2 = cb[lb+2] - cb[ib+2];
        float mu = s_mxb[n] + d0*rr[0] + d1*rr[1] + d2*rr[2];
        float ss = s_ssxb[n]
                 + 2.0f*(d0*s_XW[n][0] + d1*s_XW[n][1] + d2*s_XW[n][2])
                 + d0*(Gr[0]*d0 + Gr[1]*d1 + Gr[2]*d2)
                 + d1*(Gr[3]*d0 + Gr[4]*d1 + Gr[5]*d2)
                 + d2*(Gr[6]*d0 + Gr[7]*d1 + Gr[8]*d2);
        float var = ss*(1.0f/128.0f) - mu*mu;
        float rstd = rsqrtf(var + 1e-5f);
        s_mu[l] = mu; s_rstd[l] = rstd;
        float rm = rstd*mu;
        bool msk = (mk[n] == 0);
        #pragma unroll
        for (int h = 0; h < 8; h++){
            float s = rstd*(s_QXk[h][n] + d0*s_qMk[h][0] + d1*s_qMk[h][1] + d2*s_qMk[h][2])
                    - rm*s_quk[h] + s_qck[h];
            s *= 0.25f;
            s_sc[h][l] = msk ? -1e9f : s;
        }
    }
    __syncthreads();

    {
        int h = tid >> 5, lane = tid & 31;
        float m = -3.4e38f;
        for (int l = lane; l < LL; l += 32) m = fmaxf(m, s_sc[h][l]);
        #pragma unroll
        for (int o = 16; o; o >>= 1) m = fmaxf(m, __shfl_xor_sync(0xffffffffu, m, o));
        float sum = 0.0f;
        for (int l = lane; l < LL; l += 32){
            float e = __expf(s_sc[h][l] - m);
            s_sc[h][l] = e;
            sum += e;
        }
        #pragma unroll
        for (int o = 16; o; o >>= 1) sum += __shfl_xor_sync(0xffffffffu, sum, o);
        float inv = 1.0f / sum;
        for (int l = lane; l < LL; l += 32) s_sc[h][l] *= inv;
    }
    __syncthreads();

    {
        int h = tid >> 5, n = tid & 31;
        float A = 0.f, B0 = 0.f, B1 = 0.f, B2 = 0.f, Gp = 0.f;
        #pragma unroll 1
        for (int c = 0; c < NCC; c++){
            int l = c*32 + n;
            float w = s_sc[h][l];
            float wr = w * s_rstd[l];
            int lb = l*3, ib = (c*32 + i)*3;
            float d0 = cb[lb] - cb[ib], d1 = cb[lb+1] - cb[ib+1], d2 = cb[lb+2] - cb[ib+2];
            A += wr;
            B0 = fmaf(wr, d0, B0); B1 = fmaf(wr, d1, B1); B2 = fmaf(wr, d2, B2);
            Gp = fmaf(-wr, s_mu[l], Gp);
        }
        s_A[h][n] = A;
        B0 = warpSum(B0); B1 = warpSum(B1); B2 = warpSum(B2); Gp = warpSum(Gp);
        if (n == 0){ s_B[h][0]=B0; s_B[h][1]=B1; s_B[h][2]=B2; s_G8[h]=Gp; }
    }
    __syncthreads();

    if (tid < 128){
        int d = tid, h = d >> 4;
        float acc = g_cv[d] + s_G8[h]*g_uv[d]
                  + s_B[h][0]*g_Mv[d] + s_B[h][1]*g_Mv[DD+d] + s_B[h][2]*g_Mv[2*DD+d];
        const float* Xvb = g_Xv + b*32*DD;
        #pragma unroll 8
        for (int n = 0; n < 32; n++) acc = fmaf(s_A[h][n], Xvb[n*DD + d], acc);
        s_atts[d] = acc;
    }
    __syncthreads();

    {
        int part = tid >> 7, dp = tid & 127;
        float o = 0.0f;
        int k0 = part*64;
        #pragma unroll
        for (int k = 0; k < 64; k++) o = fmaf(s_atts[k0+k], Wo[(k0+k)*DD + dp], o);
        s_op[part][dp] = o;
    }
    __syncthreads();
    if (tid < 128){
        float y = g_xb[bid*DD + tid] + s_op[0][tid] + s_op[1][tid] + bo[tid];
        g_y[bid*DD + tid] = y;
        s_atts[tid] = y;
        float s = warpSum(y), s2 = warpSum(y*y);
        if ((tid & 31) == 0){ rsm[tid>>5][0] = s; rsm[tid>>5][1] = s2; }
    }
    __syncthreads();
    if (tid == 0){
        float s  = rsm[0][0]+rsm[1][0]+rsm[2][0]+rsm[3][0];
        float s2 = rsm[0][1]+rsm[1][1]+rsm[2][1]+rsm[3][1];
        float m = s * (1.0f/128.0f);
        stat[0] = m;
        stat[1] = rsqrtf(s2*(1.0f/128.0f) - m*m + 1e-5f);
    }
    __syncthreads();
    if (tid < 128)
        g_hn2[bid*DD + tid] = (s_atts[tid] - stat[0])*stat[1]*g2[tid] + b2[tid];
}

// ================= K3: FFN, 4 rows per block (32 blocks x 512) ================
__global__ void __launch_bounds__(512)
k_ffn(const float* __restrict__ W1, const float* __restrict__ bf1,
      const float* __restrict__ W2, const float* __restrict__ bf2,
      float* __restrict__ out)
{
    __shared__ float hs[4][128];
    __shared__ float zs[4][512];
    __shared__ float red[4][4][128];     // [part][row][d]
    int r0 = blockIdx.x * 4;
    int tid = threadIdx.x;

    { int r = tid >> 7, d = tid & 127; hs[r][d] = g_hn2[(r0+r)*DD + d]; }
    __syncthreads();

    // stage 1: z[r][j] = relu(hn2[r] @ W1[:,j] + bf1[j]); j = tid, coalesced W1
    {
        int j = tid;
        float z0=0.f, z1=0.f, z2=0.f, z3=0.f;
        #pragma unroll 8
        for (int k = 0; k < 128; k++){
            float w = W1[k*DFF + j];
            z0 = fmaf(hs[0][k], w, z0); z1 = fmaf(hs[1][k], w, z1);
            z2 = fmaf(hs[2][k], w, z2); z3 = fmaf(hs[3][k], w, z3);
        }
        float bb = bf1[j];
        zs[0][j] = fmaxf(z0+bb, 0.f); zs[1][j] = fmaxf(z1+bb, 0.f);
        zs[2][j] = fmaxf(z2+bb, 0.f); zs[3][j] = fmaxf(z3+bb, 0.f);
    }
    __syncthreads();

    // stage 2: out[r][d] += z[r] @ W2[:,d]; 4-way k-split, coalesced W2
    {
        int part = tid >> 7, d = tid & 127;
        int j0 = part * 128;
        float o0=0.f, o1=0.f, o2=0.f, o3=0.f;
        #pragma unroll 4
        for (int jj = 0; jj < 128; jj++){
            float w = W2[(j0+jj)*DD + d];
            o0 = fmaf(zs[0][j0+jj], w, o0); o1 = fmaf(zs[1][j0+jj], w, o1);
            o2 = fmaf(zs[2][j0+jj], w, o2); o3 = fmaf(zs[3][j0+jj], w, o3);
        }
        red[part][0][d]=o0; red[part][1][d]=o1; red[part][2][d]=o2; red[part][3][d]=o3;
    }
    __syncthreads();
    {
        int r = tid >> 7, d = tid & 127;
        int row = r0 + r;
        out[row*DD + d] = g_y[row*DD + d]
                        + red[0][r][d] + red[1][r][d] + red[2][r][d] + red[3][r][d]
                        + bf2[d];
    }
}

// ---------------- launch ------------------------------------------------------
extern "C" void kernel_launch(void* const* d_in, const int* in_sizes, int n_in,
                              void* d_out, int out_size)
{
    const float* x      = (const float*)d_in[0];
    const int*   mask   = (const int*)  d_in[1];
    const float* coords = (const float*)d_in[2];
    const float* Wp = (const float*)d_in[3],  *bp  = (const float*)d_in[4];
    const float* Wq = (const float*)d_in[5],  *bq  = (const float*)d_in[6];
    const float* Wk = (const float*)d_in[7],  *bk  = (const float*)d_in[8];
    const float* Wv = (const float*)d_in[9],  *bv  = (const float*)d_in[10];
    const float* Wo = (const float*)d_in[11], *bo  = (const float*)d_in[12];
    const float* g1 = (const float*)d_in[13], *b1  = (const float*)d_in[14];
    const float* g2 = (const float*)d_in[15], *b2  = (const float*)d_in[16];
    const float* W1 = (const float*)d_in[17], *bf1 = (const float*)d_in[18];
    const float* W2 = (const float*)d_in[19], *bf2 = (const float*)d_in[20];
    float* out = (float*)d_out;

    float *uq_p, *cq_p;
    cudaGetSymbolAddress((void**)&uq_p, g_uq);
    cudaGetSymbolAddress((void**)&cq_p, g_cq);

    k_pre  <<<55, 256>>>(x, Wp, bp, Wq, bq, Wk, bk, Wv, bv, g1, b1);
    k_attn2<<<NR, 256>>>(coords, mask, Wo, bo, uq_p, cq_p, g2, b2);
    k_ffn  <<<32, 512>>>(W1, bf1, W2, bf2, out);
}

// round 7
// speedup vs baseline: 1.1846x; 1.1846x over previous
#include <cuda_runtime.h>
#include <math.h>

#define BB 4
#define NN 32
#define DD 128
#define HH 8
#define NCC 27
#define DFF 512
#define LL (NCC*NN)        // 864
#define NR (BB*NN)         // 128 token rows
#define GRID NR
#define TPB 256

// ---------------- scratch (static device globals; no allocation) -------------
__device__ float g_mxb[NR], g_ssxb[NR];
__device__ float g_XW[NR*3];
__device__ __align__(16) float g_Xk[NR*DD], g_Xv[NR*DD];
__device__ float g_Mk[3*DD], g_Mv[3*DD];
__device__ float g_uq[DD], g_uk[DD], g_uv[DD];
__device__ float g_cq[DD], g_ck[DD], g_cv[DD];
__device__ float g_G[9], g_rs[3];
__device__ unsigned g_tick;            // monotonic barrier ticket (never reset)

__inline__ __device__ float warpSum(float v){
    #pragma unroll
    for (int o = 16; o; o >>= 1) v += __shfl_down_sync(0xffffffffu, v, o);
    return v;
}

__global__ void __launch_bounds__(TPB, 1)
k_fused(const float* __restrict__ x, const int* __restrict__ mask,
        const float* __restrict__ coords,
        const float* __restrict__ Wp, const float* __restrict__ bp,
        const float* __restrict__ Wq, const float* __restrict__ bq,
        const float* __restrict__ Wk, const float* __restrict__ bk,
        const float* __restrict__ Wv, const float* __restrict__ bv,
        const float* __restrict__ Wo, const float* __restrict__ bo,
        const float* __restrict__ g1, const float* __restrict__ b1,
        const float* __restrict__ g2, const float* __restrict__ b2,
        const float* __restrict__ W1, const float* __restrict__ bf1,
        const float* __restrict__ W2, const float* __restrict__ bf2,
        float* __restrict__ out)
{
    __shared__ float s_sc[HH][LL];          // 27.6 KB, heavily overlaid
    __shared__ float s_mu[LL], s_rstd[LL];  // 6.9 KB
    __shared__ float s_xb[128], s_Xq[128], s_yrow[128], s_hn2[128];
    __shared__ float s_QXk[HH][32];
    __shared__ float s_qMk[HH][4], s_quk[HH], s_qck[HH];
    __shared__ float s_A[HH][32], s_B[HH][4], s_G8[HH];
    __shared__ float s_mxb[32], s_ssxb[32], s_XW[32][3];
    __shared__ float rsm[4][2], stat[2];
    __shared__ int   mk[32];

    float* s_scf = &s_sc[0][0];
    int bid = blockIdx.x, tid = threadIdx.x;
    int b = bid >> 5, i = bid & 31;

    // ===================== PHASE 1: precomputes ==============================
    {
        float* part  = s_scf;          // [2][128] partial-reduce buffer
        float* s_xbg = s_scf + 256;    // xb * g1
        float* s_aux = s_scf + 384;    // aux vector for this block's aux unit

        if (tid < 128){
            float xv = x[bid*DD + tid] + bp[tid];
            s_xb[tid]  = xv;
            s_xbg[tid] = xv * g1[tid];
        }
        __syncthreads();

        // per-row stats: 4 warps over 128 elems
        if (tid < 128){
            float v = s_xb[tid];
            float p0 = v * Wp[tid], p1 = v * Wp[DD+tid], p2 = v * Wp[2*DD+tid];
            float s = warpSum(v), ss = warpSum(v*v);
            p0 = warpSum(p0); p1 = warpSum(p1); p2 = warpSum(p2);
            int lane = tid & 31, w = tid >> 5;
            if (lane == 0){
                rsm[w][0] = s; rsm[w][1] = ss;
                s_XW[w][0] = p0; s_XW[w][1] = p1; s_XW[w][2] = p2;  // temp reuse
            }
        }
        __syncthreads();
        if (tid == 0){
            g_mxb[bid]  = (rsm[0][0]+rsm[1][0]+rsm[2][0]+rsm[3][0]) * (1.0f/128.0f);
            g_ssxb[bid] =  rsm[0][1]+rsm[1][1]+rsm[2][1]+rsm[3][1];
        } else if (tid < 4){
            g_XW[bid*3 + (tid-1)] = s_XW[0][tid-1]+s_XW[1][tid-1]+s_XW[2][tid-1]+s_XW[3][tid-1];
        }

        // row GEMMs: Xq (smem), Xk, Xv (global); 2-way k-split per output
        int half = tid >> 7, j = tid & 127, k0 = half*64;
        #pragma unroll 1
        for (int m = 0; m < 3; m++){
            const float* W = (m==0) ? Wq : ((m==1) ? Wk : Wv);
            float acc = 0.0f;
            #pragma unroll 8
            for (int kk = 0; kk < 64; kk++)
                acc = fmaf(s_xbg[k0+kk], W[(k0+kk)*DD + j], acc);
            part[half*128 + j] = acc;
            __syncthreads();
            if (tid < 128){
                float v = part[tid] + part[128+tid];
                if      (m == 0) s_Xq[tid] = v;
                else if (m == 1) g_Xk[bid*DD + tid] = v;
                else             g_Xv[bid*DD + tid] = v;
            }
            __syncthreads();
        }

        // aux units on blocks 0..12
        if (bid < 12){
            // units: 0-2 Mk rows, 3-5 Mv rows, 6-8 u(q,k,v), 9-11 c(q,k,v)
            int unit = bid;
            const float* W; float* O; const float* bias = 0;
            if (tid < 128){
                if (unit < 6){
                    int a = unit % 3;
                    s_aux[tid] = Wp[a*DD + tid] * g1[tid];
                } else if (unit < 9){
                    s_aux[tid] = g1[tid];
                } else {
                    s_aux[tid] = b1[tid];
                }
            }
            if (unit < 3)      { W = Wk; O = g_Mk + (unit%3)*DD; }
            else if (unit < 6) { W = Wv; O = g_Mv + (unit%3)*DD; }
            else if (unit == 6){ W = Wq; O = g_uq; }
            else if (unit == 7){ W = Wk; O = g_uk; }
            else if (unit == 8){ W = Wv; O = g_uv; }
            else if (unit == 9){ W = Wq; O = g_cq; bias = bq; }
            else if (unit ==10){ W = Wk; O = g_ck; bias = bk; }
            else               { W = Wv; O = g_cv; bias = bv; }
            __syncthreads();
            float acc = 0.0f;
            #pragma unroll 8
            for (int kk = 0; kk < 64; kk++)
                acc = fmaf(s_aux[k0+kk], W[(k0+kk)*DD + j], acc);
            part[half*128 + j] = acc;
            __syncthreads();
            if (tid < 128)
                O[tid] = part[tid] + part[128+tid] + (bias ? bias[tid] : 0.0f);
        } else if (bid == 12){
            // G = Wp Wp^T (9), rs (3): warp per output
            int w = tid >> 5, lane = tid & 31;
            for (int o = w; o < 12; o += 8){
                float acc = 0.0f;
                if (o < 9){
                    int a = o/3, c = o%3;
                    #pragma unroll
                    for (int q4 = 0; q4 < 4; q4++){
                        int k = lane + q4*32;
                        acc = fmaf(Wp[a*DD+k], Wp[c*DD+k], acc);
                    }
                    acc = warpSum(acc);
                    if (lane == 0) g_G[o] = acc;
                } else {
                    int a = o - 9;
                    #pragma unroll
                    for (int q4 = 0; q4 < 4; q4++) acc += Wp[a*DD + lane + q4*32];
                    acc = warpSum(acc);
                    if (lane == 0) g_rs[a] = acc;
                }
            }
        }
    }

    // ===================== GLOBAL BARRIER (monotonic ticket) ==================
    __syncthreads();
    if (tid == 0){
        __threadfence();
        unsigned my = atomicAdd(&g_tick, 1u);
        unsigned target = (my / GRID + 1u) * GRID;
        while (atomicAdd(&g_tick, 0u) < target) { }
        __threadfence();
    }
    __syncthreads();

    // ===================== PHASE 2: attention (factored) =====================
    const float* cb = coords + b*LL*3;
    {
        float* s_q = s_scf;   // temp overlay until scores are written

        if (tid < 32){
            mk[tid]     = mask[b*32 + tid];
            s_mxb[tid]  = g_mxb[b*32 + tid];
            s_ssxb[tid] = g_ssxb[b*32 + tid];
        }
        for (int t = tid; t < 96; t += TPB) s_XW[t/3][t%3] = g_XW[b*96 + t];

        float mu_i = g_mxb[bid];
        float rstd_i = rsqrtf(g_ssxb[bid]*(1.0f/128.0f) - mu_i*mu_i + 1e-5f);
        if (tid < 128)
            s_q[tid] = rstd_i*s_Xq[tid] - rstd_i*mu_i*g_uq[tid] + g_cq[tid];
        __syncthreads();

        {
            int h = tid >> 5, n = tid & 31;
            float acc = 0.0f;
            #pragma unroll
            for (int j = 0; j < 16; j++)
                acc = fmaf(s_q[h*16+j], g_Xk[(b*32+n)*DD + h*16 + j], acc);
            s_QXk[h][n] = acc;
        }
        if (tid < 24){
            int h = tid/3, a = tid%3;
            float acc = 0.0f;
            #pragma unroll
            for (int j = 0; j < 16; j++) acc = fmaf(s_q[h*16+j], g_Mk[a*DD + h*16 + j], acc);
            s_qMk[h][a] = acc;
        } else if (tid < 32){
            int h = tid - 24;
            float acc = 0.0f;
            #pragma unroll
            for (int j = 0; j < 16; j++) acc = fmaf(s_q[h*16+j], g_uk[h*16+j], acc);
            s_quk[h] = acc;
        } else if (tid < 40){
            int h = tid - 32;
            float acc = 0.0f;
            #pragma unroll
            for (int j = 0; j < 16; j++) acc = fmaf(s_q[h*16+j], g_ck[h*16+j], acc);
            s_qck[h] = acc;
        }
        __syncthreads();
    }

    {
        float Gr[9], rr[3];
        #pragma unroll
        for (int a = 0; a < 9; a++) Gr[a] = g_G[a];
        #pragma unroll
        for (int a = 0; a < 3; a++) rr[a] = g_rs[a] * (1.0f/128.0f);

        for (int l = tid; l < LL; l += TPB){
            int c = l >> 5, n = l & 31;
            int lb = l*3, ib = (c*32 + i)*3;
            float d0 = cb[lb]   - cb[ib];
            float d1 = cb[lb+1] - cb[ib+1];
            float d2 = cb[lb+2] - cb[ib+2];
            float mu = s_mxb[n] + d0*rr[0] + d1*rr[1] + d2*rr[2];
            float ss = s_ssxb[n]
                     + 2.0f*(d0*s_XW[n][0] + d1*s_XW[n][1] + d2*s_XW[n][2])
                     + d0*(Gr[0]*d0 + Gr[1]*d1 + Gr[2]*d2)
                     + d1*(Gr[3]*d0 + Gr[4]*d1 + Gr[5]*d2)
                     + d2*(Gr[6]*d0 + Gr[7]*d1 + Gr[8]*d2);
            float var = ss*(1.0f/128.0f) - mu*mu;
            float rstd = rsqrtf(var + 1e-5f);
            s_mu[l] = mu; s_rstd[l] = rstd;
            float rm = rstd*mu;
            bool msk = (mk[n] == 0);
            #pragma unroll
            for (int h = 0; h < 8; h++){
                float s = rstd*(s_QXk[h][n] + d0*s_qMk[h][0] + d1*s_qMk[h][1] + d2*s_qMk[h][2])
                        - rm*s_quk[h] + s_qck[h];
                s *= 0.25f;
                s_sc[h][l] = msk ? -1e9f : s;
            }
        }
        __syncthreads();

        // softmax: warp per head
        {
            int h = tid >> 5, lane = tid & 31;
            float m = -3.4e38f;
            for (int l = lane; l < LL; l += 32) m = fmaxf(m, s_sc[h][l]);
            #pragma unroll
            for (int o = 16; o; o >>= 1) m = fmaxf(m, __shfl_xor_sync(0xffffffffu, m, o));
            float sum = 0.0f;
            for (int l = lane; l < LL; l += 32){
                float e = __expf(s_sc[h][l] - m);
                s_sc[h][l] = e;
                sum += e;
            }
            #pragma unroll
            for (int o = 16; o; o >>= 1) sum += __shfl_xor_sync(0xffffffffu, sum, o);
            float inv = 1.0f / sum;
            for (int l = lane; l < LL; l += 32) s_sc[h][l] *= inv;
        }
        __syncthreads();

        // V aggregates
        {
            int h = tid >> 5, n = tid & 31;
            float A = 0.f, B0 = 0.f, B1 = 0.f, B2 = 0.f, Gp = 0.f;
            #pragma unroll 1
            for (int c = 0; c < NCC; c++){
                int l = c*32 + n;
                float wr = s_sc[h][l] * s_rstd[l];
                int lb = l*3, ib = (c*32 + i)*3;
                float d0 = cb[lb] - cb[ib], d1 = cb[lb+1] - cb[ib+1], d2 = cb[lb+2] - cb[ib+2];
                A += wr;
                B0 = fmaf(wr, d0, B0); B1 = fmaf(wr, d1, B1); B2 = fmaf(wr, d2, B2);
                Gp = fmaf(-wr, s_mu[l], Gp);
            }
            s_A[h][n] = A;
            B0 = warpSum(B0); B1 = warpSum(B1); B2 = warpSum(B2); Gp = warpSum(Gp);
            if (n == 0){ s_B[h][0]=B0; s_B[h][1]=B1; s_B[h][2]=B2; s_G8[h]=Gp; }
        }
        __syncthreads();
    }

    // scores no longer needed -> overlay atts/op on s_sc
    {
        float* s_atts = s_scf;
        float* s_op   = s_scf + 128;   // [2][128]

        if (tid < 128){
            int d = tid, h = d >> 4;
            float acc = g_cv[d] + s_G8[h]*g_uv[d]
                      + s_B[h][0]*g_Mv[d] + s_B[h][1]*g_Mv[DD+d] + s_B[h][2]*g_Mv[2*DD+d];
            const float* Xvb = g_Xv + b*32*DD;
            #pragma unroll 8
            for (int n = 0; n < 32; n++) acc = fmaf(s_A[h][n], Xvb[n*DD + d], acc);
            s_atts[d] = acc;
        }
        __syncthreads();

        {
            int part = tid >> 7, dp = tid & 127;
            float o = 0.0f;
            int k0 = part*64;
            #pragma unroll
            for (int k = 0; k < 64; k++) o = fmaf(s_atts[k0+k], Wo[(k0+k)*DD + dp], o);
            s_op[part*128 + dp] = o;
        }
        __syncthreads();
        if (tid < 128){
            float y = s_xb[tid] + s_op[tid] + s_op[128+tid] + bo[tid];
            s_yrow[tid] = y;
            float s = warpSum(y), s2 = warpSum(y*y);
            if ((tid & 31) == 0){ rsm[tid>>5][0] = s; rsm[tid>>5][1] = s2; }
        }
        __syncthreads();
        if (tid == 0){
            float s  = rsm[0][0]+rsm[1][0]+rsm[2][0]+rsm[3][0];
            float s2 = rsm[0][1]+rsm[1][1]+rsm[2][1]+rsm[3][1];
            float m = s * (1.0f/128.0f);
            stat[0] = m;
            stat[1] = rsqrtf(s2*(1.0f/128.0f) - m*m + 1e-5f);
        }
        __syncthreads();
        if (tid < 128)
            s_hn2[tid] = (s_yrow[tid] - stat[0])*stat[1]*g2[tid] + b2[tid];
        __syncthreads();
    }

    // ===================== PHASE 3: FFN (same row, no barrier) ================
    {
        float* zs  = s_scf;            // 512
        float* red = s_scf + 512;      // [2][128]

        // stage 1: thread t -> cols t and t+256 (independent chains, coalesced)
        {
            float z0 = 0.f, z1 = 0.f;
            #pragma unroll 8
            for (int k = 0; k < 128; k++){
                float h = s_hn2[k];
                z0 = fmaf(h, W1[k*DFF + tid],       z0);
                z1 = fmaf(h, W1[k*DFF + tid + 256], z1);
            }
            zs[tid]       = fmaxf(z0 + bf1[tid],       0.0f);
            zs[tid + 256] = fmaxf(z1 + bf1[tid + 256], 0.0f);
        }
        __syncthreads();

        // stage 2: 2-way k-split, dual accumulators
        {
            int half = tid >> 7, d = tid & 127;
            int j0 = half * 256;
            float o0 = 0.f, o1 = 0.f;
            #pragma unroll 4
            for (int jj = 0; jj < 256; jj += 2){
                o0 = fmaf(zs[j0+jj],   W2[(j0+jj)*DD + d],   o0);
                o1 = fmaf(zs[j0+jj+1], W2[(j0+jj+1)*DD + d], o1);
            }
            red[half*128 + d] = o0 + o1;
        }
        __syncthreads();
        if (tid < 128)
            out[bid*DD + tid] = s_yrow[tid] + red[tid] + red[128+tid] + bf2[tid];
    }
}

// ---------------- launch ------------------------------------------------------
extern "C" void kernel_launch(void* const* d_in, const int* in_sizes, int n_in,
                              void* d_out, int out_size)
{
    const float* x      = (const float*)d_in[0];
    const int*   mask   = (const int*)  d_in[1];
    const float* coords = (const float*)d_in[2];
    const float* Wp = (const float*)d_in[3],  *bp  = (const float*)d_in[4];
    const float* Wq = (const float*)d_in[5],  *bq  = (const float*)d_in[6];
    const float* Wk = (const float*)d_in[7],  *bk  = (const float*)d_in[8];
    const float* Wv = (const float*)d_in[9],  *bv  = (const float*)d_in[10];
    const float* Wo = (const float*)d_in[11], *bo  = (const float*)d_in[12];
    const float* g1 = (const float*)d_in[13], *b1  = (const float*)d_in[14];
    const float* g2 = (const float*)d_in[15], *b2  = (const float*)d_in[16];
    const float* W1 = (const float*)d_in[17], *bf1 = (const float*)d_in[18];
    const float* W2 = (const float*)d_in[19], *bf2 = (const float*)d_in[20];
    float* out = (float*)d_out;

    k_fused<<<GRID, TPB>>>(x, mask, coords, Wp, bp, Wq, bq, Wk, bk, Wv, bv,
                           Wo, bo, g1, b1, g2, b2, W1, bf1, W2, bf2, out);
}

// round 8
// speedup vs baseline: 1.2623x; 1.0656x over previous
#include <cuda_runtime.h>
#include <math.h>

#define BB 4
#define NN 32
#define DD 128
#define HH 8
#define NCC 27
#define DFF 512
#define LL (NCC*NN)        // 864
#define NR (BB*NN)         // 128 token rows
#define GRID NR
#define TPB 512

// ---------------- scratch (static device globals; no allocation) -------------
__device__ float g_mxb[NR], g_ssxb[NR];
__device__ float g_XW[NR*3];
__device__ __align__(16) float g_Xk[NR*DD], g_Xv[NR*DD];
__device__ float g_Mk[3*DD], g_Mv[3*DD];
__device__ float g_uq[DD], g_uk[DD], g_uv[DD];
__device__ float g_cq[DD], g_ck[DD], g_cv[DD];
__device__ float g_G[9], g_rs[3];
__device__ unsigned g_tick;            // monotonic barrier ticket (never reset)

__inline__ __device__ float warpSum(float v){
    #pragma unroll
    for (int o = 16; o; o >>= 1) v += __shfl_down_sync(0xffffffffu, v, o);
    return v;
}

__global__ void __launch_bounds__(TPB, 1)
k_fused(const float* __restrict__ x, const int* __restrict__ mask,
        const float* __restrict__ coords,
        const float* __restrict__ Wp, const float* __restrict__ bp,
        const float* __restrict__ Wq, const float* __restrict__ bq,
        const float* __restrict__ Wk, const float* __restrict__ bk,
        const float* __restrict__ Wv, const float* __restrict__ bv,
        const float* __restrict__ Wo, const float* __restrict__ bo,
        const float* __restrict__ g1, const float* __restrict__ b1,
        const float* __restrict__ g2, const float* __restrict__ b2,
        const float* __restrict__ W1, const float* __restrict__ bf1,
        const float* __restrict__ W2, const float* __restrict__ bf2,
        float* __restrict__ out)
{
    __shared__ float s_sc[HH][LL];          // 27.6 KB, heavily overlaid
    __shared__ float s_mu[LL], s_rstd[LL];  // 6.9 KB
    __shared__ float s_xb[128], s_Xq[128], s_yrow[128], s_hn2[128];
    __shared__ float s_QXk[HH][32];
    __shared__ float s_qMk[HH][4], s_quk[HH], s_qck[HH];
    __shared__ float s_A[HH][32], s_B[HH][4], s_G8[HH];
    __shared__ float s_Ap[2][HH][32], s_Bp[2][HH][4], s_Gp8[2][HH];
    __shared__ float s_mxb[32], s_ssxb[32], s_XW[32][3];
    __shared__ float rsm[4][2], stat[2];
    __shared__ int   mk[32];

    float* s_scf = &s_sc[0][0];
    int bid = blockIdx.x, tid = threadIdx.x;
    int b = bid >> 5, i = bid & 31;

    // ===================== PHASE 1: precomputes ==============================
    {
        float* s_xbg = s_scf;          // 128
        float* s_aux = s_scf + 128;    // 128

        if (tid < 128){
            float xv = x[bid*DD + tid] + bp[tid];
            s_xb[tid]  = xv;
            s_xbg[tid] = xv * g1[tid];
            // per-row stats from register value
            float p0 = xv * Wp[tid], p1 = xv * Wp[DD+tid], p2 = xv * Wp[2*DD+tid];
            float s = warpSum(xv), ss = warpSum(xv*xv);
            p0 = warpSum(p0); p1 = warpSum(p1); p2 = warpSum(p2);
            int lane = tid & 31, w = tid >> 5;
            if (lane == 0){
                rsm[w][0] = s; rsm[w][1] = ss;
                s_XW[w][0] = p0; s_XW[w][1] = p1; s_XW[w][2] = p2;  // temp reuse
            }
        } else if (tid >= 384 && bid < 12){
            int t = tid - 384;
            int unit = bid;
            if (unit < 6)      s_aux[t] = Wp[(unit%3)*DD + t] * g1[t];
            else if (unit < 9) s_aux[t] = g1[t];
            else               s_aux[t] = b1[t];
        }
        __syncthreads();

        if (tid == 0){
            g_mxb[bid]  = (rsm[0][0]+rsm[1][0]+rsm[2][0]+rsm[3][0]) * (1.0f/128.0f);
            g_ssxb[bid] =  rsm[0][1]+rsm[1][1]+rsm[2][1]+rsm[3][1];
        } else if (tid < 4){
            g_XW[bid*3 + (tid-1)] = s_XW[0][tid-1]+s_XW[1][tid-1]+s_XW[2][tid-1]+s_XW[3][tid-1];
        }

        if (tid < 384){
            // row GEMMs: all three matrices in parallel, full-k chain per thread
            int m = tid >> 7, j = tid & 127;
            const float* W = (m==0) ? Wq : ((m==1) ? Wk : Wv);
            float acc = 0.0f;
            #pragma unroll 8
            for (int k = 0; k < 128; k++)
                acc = fmaf(s_xbg[k], W[k*DD + j], acc);
            if      (m == 0) s_Xq[j] = acc;
            else if (m == 1) g_Xk[bid*DD + j] = acc;
            else             g_Xv[bid*DD + j] = acc;
        } else if (bid < 12){
            // aux unit: bid selects unit, thread computes one output col
            int j = tid - 384;
            int unit = bid;
            const float* W; float* O; const float* bias = 0;
            if (unit < 3)      { W = Wk; O = g_Mk + unit*DD; }
            else if (unit < 6) { W = Wv; O = g_Mv + (unit-3)*DD; }
            else if (unit == 6){ W = Wq; O = g_uq; }
            else if (unit == 7){ W = Wk; O = g_uk; }
            else if (unit == 8){ W = Wv; O = g_uv; }
            else if (unit == 9){ W = Wq; O = g_cq; bias = bq; }
            else if (unit ==10){ W = Wk; O = g_ck; bias = bk; }
            else               { W = Wv; O = g_cv; bias = bv; }
            float acc = 0.0f;
            #pragma unroll 8
            for (int k = 0; k < 128; k++)
                acc = fmaf(s_aux[k], W[k*DD + j], acc);
            O[j] = acc + (bias ? bias[j] : 0.0f);
        } else if (bid == 12){
            // G = Wp Wp^T (9), rs (3): warps 12..15, outputs strided by 4
            int w = (tid - 384) >> 5, lane = tid & 31;
            for (int o = w; o < 12; o += 4){
                float acc = 0.0f;
                if (o < 9){
                    int a = o/3, c = o%3;
                    #pragma unroll
                    for (int q4 = 0; q4 < 4; q4++){
                        int k = lane + q4*32;
                        acc = fmaf(Wp[a*DD+k], Wp[c*DD+k], acc);
                    }
                    acc = warpSum(acc);
                    if (lane == 0) g_G[o] = acc;
                } else {
                    int a = o - 9;
                    #pragma unroll
                    for (int q4 = 0; q4 < 4; q4++) acc += Wp[a*DD + lane + q4*32];
                    acc = warpSum(acc);
                    if (lane == 0) g_rs[a] = acc;
                }
            }
        }
    }

    // ===================== GLOBAL BARRIER (monotonic ticket) ==================
    __syncthreads();
    if (tid == 0){
        __threadfence();
        unsigned my = atomicAdd(&g_tick, 1u);
        unsigned target = (my / GRID + 1u) * GRID;
        while (atomicAdd(&g_tick, 0u) < target) { }
        __threadfence();
    }
    __syncthreads();

    // ===================== PHASE 2: attention (factored) =====================
    const float* cb = coords + b*LL*3;
    {
        float* s_q = s_scf;   // temp overlay until scores are written

        if (tid < 32){
            mk[tid]     = mask[b*32 + tid];
            s_mxb[tid]  = g_mxb[b*32 + tid];
            s_ssxb[tid] = g_ssxb[b*32 + tid];
        }
        if (tid >= 416 && tid < 512){
            int t = tid - 416;
            s_XW[t/3][t%3] = g_XW[b*96 + t];
        }

        float mu_i = g_mxb[bid];
        float rstd_i = rsqrtf(g_ssxb[bid]*(1.0f/128.0f) - mu_i*mu_i + 1e-5f);
        if (tid >= 128 && tid < 256){
            int d = tid - 128;
            s_q[d] = rstd_i*s_Xq[d] - rstd_i*mu_i*g_uq[d] + g_cq[d];
        }
        __syncthreads();

        if (tid < 256){
            int h = tid >> 5, n = tid & 31;
            float acc = 0.0f;
            #pragma unroll
            for (int j = 0; j < 16; j++)
                acc = fmaf(s_q[h*16+j], g_Xk[(b*32+n)*DD + h*16 + j], acc);
            s_QXk[h][n] = acc;
        } else if (tid < 280){
            int t = tid - 256;
            int h = t/3, a = t%3;
            float acc = 0.0f;
            #pragma unroll
            for (int j = 0; j < 16; j++) acc = fmaf(s_q[h*16+j], g_Mk[a*DD + h*16 + j], acc);
            s_qMk[h][a] = acc;
        } else if (tid < 288){
            int h = tid - 280;
            float acc = 0.0f;
            #pragma unroll
            for (int j = 0; j < 16; j++) acc = fmaf(s_q[h*16+j], g_uk[h*16+j], acc);
            s_quk[h] = acc;
        } else if (tid < 296){
            int h = tid - 288;
            float acc = 0.0f;
            #pragma unroll
            for (int j = 0; j < 16; j++) acc = fmaf(s_q[h*16+j], g_ck[h*16+j], acc);
            s_qck[h] = acc;
        }
        __syncthreads();
    }

    {
        float Gr[9], rr[3];
        #pragma unroll
        for (int a = 0; a < 9; a++) Gr[a] = g_G[a];
        #pragma unroll
        for (int a = 0; a < 3; a++) rr[a] = g_rs[a] * (1.0f/128.0f);

        for (int l = tid; l < LL; l += TPB){
            int c = l >> 5, n = l & 31;
            int lb = l*3, ib = (c*32 + i)*3;
            float d0 = cb[lb]   - cb[ib];
            float d1 = cb[lb+1] - cb[ib+1];
            float d2 = cb[lb+2] - cb[ib+2];
            float mu = s_mxb[n] + d0*rr[0] + d1*rr[1] + d2*rr[2];
            float ss = s_ssxb[n]
                     + 2.0f*(d0*s_XW[n][0] + d1*s_XW[n][1] + d2*s_XW[n][2])
                     + d0*(Gr[0]*d0 + Gr[1]*d1 + Gr[2]*d2)
                     + d1*(Gr[3]*d0 + Gr[4]*d1 + Gr[5]*d2)
                     + d2*(Gr[6]*d0 + Gr[7]*d1 + Gr[8]*d2);
            float var = ss*(1.0f/128.0f) - mu*mu;
            float rstd = rsqrtf(var + 1e-5f);
            s_mu[l] = mu; s_rstd[l] = rstd;
            float rm = rstd*mu;
            bool msk = (mk[n] == 0);
            #pragma unroll
            for (int h = 0; h < 8; h++){
                float s = rstd*(s_QXk[h][n] + d0*s_qMk[h][0] + d1*s_qMk[h][1] + d2*s_qMk[h][2])
                        - rm*s_quk[h] + s_qck[h];
                s *= 0.25f;
                s_sc[h][l] = msk ? -1e9f : s;
            }
        }
        __syncthreads();

        // softmax: warp per head (warps 0-7)
        if (tid < 256){
            int h = tid >> 5, lane = tid & 31;
            float m = -3.4e38f;
            for (int l = lane; l < LL; l += 32) m = fmaxf(m, s_sc[h][l]);
            #pragma unroll
            for (int o = 16; o; o >>= 1) m = fmaxf(m, __shfl_xor_sync(0xffffffffu, m, o));
            float sum = 0.0f;
            for (int l = lane; l < LL; l += 32){
                float e = __expf(s_sc[h][l] - m);
                s_sc[h][l] = e;
                sum += e;
            }
            #pragma unroll
            for (int o = 16; o; o >>= 1) sum += __shfl_xor_sync(0xffffffffu, sum, o);
            float inv = 1.0f / sum;
            for (int l = lane; l < LL; l += 32) s_sc[h][l] *= inv;
        }
        __syncthreads();

        // V aggregates: 16 warps = (c-half, head)
        {
            int w = tid >> 5, n = tid & 31;
            int h = w & 7, ch = w >> 3;
            int c0 = ch ? 14 : 0, c1 = ch ? 27 : 14;
            float A = 0.f, B0 = 0.f, B1 = 0.f, B2 = 0.f, Gp = 0.f;
            #pragma unroll 1
            for (int c = c0; c < c1; c++){
                int l = c*32 + n;
                float wr = s_sc[h][l] * s_rstd[l];
                int lb = l*3, ib = (c*32 + i)*3;
                float d0 = cb[lb] - cb[ib], d1 = cb[lb+1] - cb[ib+1], d2 = cb[lb+2] - cb[ib+2];
                A += wr;
                B0 = fmaf(wr, d0, B0); B1 = fmaf(wr, d1, B1); B2 = fmaf(wr, d2, B2);
                Gp = fmaf(-wr, s_mu[l], Gp);
            }
            s_Ap[ch][h][n] = A;
            B0 = warpSum(B0); B1 = warpSum(B1); B2 = warpSum(B2); Gp = warpSum(Gp);
            if (n == 0){
                s_Bp[ch][h][0]=B0; s_Bp[ch][h][1]=B1; s_Bp[ch][h][2]=B2; s_Gp8[ch][h]=Gp;
            }
        }
        __syncthreads();
        if (tid < 256){
            int h = tid >> 5, n = tid & 31;
            s_A[h][n] = s_Ap[0][h][n] + s_Ap[1][h][n];
        } else if (tid < 280){
            int t = tid - 256;
            int h = t/3, a = t%3;
            s_B[h][a] = s_Bp[0][h][a] + s_Bp[1][h][a];
        } else if (tid < 288){
            int h = tid - 280;
            s_G8[h] = s_Gp8[0][h] + s_Gp8[1][h];
        }
        __syncthreads();
    }

    // scores no longer needed -> overlay atts/op on s_sc
    {
        float* s_atts = s_scf;
        float* s_op   = s_scf + 128;   // [4][128]

        if (tid < 128){
            int d = tid, h = d >> 4;
            float acc = g_cv[d] + s_G8[h]*g_uv[d]
                      + s_B[h][0]*g_Mv[d] + s_B[h][1]*g_Mv[DD+d] + s_B[h][2]*g_Mv[2*DD+d];
            const float* Xvb = g_Xv + b*32*DD;
            #pragma unroll 8
            for (int n = 0; n < 32; n++) acc = fmaf(s_A[h][n], Xvb[n*DD + d], acc);
            s_atts[d] = acc;
        }
        __syncthreads();

        {
            int part = tid >> 7, dp = tid & 127;
            float o = 0.0f;
            int k0 = part*32;
            #pragma unroll
            for (int k = 0; k < 32; k++) o = fmaf(s_atts[k0+k], Wo[(k0+k)*DD + dp], o);
            s_op[part*128 + dp] = o;
        }
        __syncthreads();
        if (tid < 128){
            float y = s_xb[tid] + s_op[tid] + s_op[128+tid] + s_op[256+tid] + s_op[384+tid] + bo[tid];
            s_yrow[tid] = y;
            float s = warpSum(y), s2 = warpSum(y*y);
            if ((tid & 31) == 0){ rsm[tid>>5][0] = s; rsm[tid>>5][1] = s2; }
        }
        __syncthreads();
        if (tid == 0){
            float s  = rsm[0][0]+rsm[1][0]+rsm[2][0]+rsm[3][0];
            float s2 = rsm[0][1]+rsm[1][1]+rsm[2][1]+rsm[3][1];
            float m = s * (1.0f/128.0f);
            stat[0] = m;
            stat[1] = rsqrtf(s2*(1.0f/128.0f) - m*m + 1e-5f);
        }
        __syncthreads();
        if (tid < 128)
            s_hn2[tid] = (s_yrow[tid] - stat[0])*stat[1]*g2[tid] + b2[tid];
        __syncthreads();
    }

    // ===================== PHASE 3: FFN (same row, no barrier) ================
    {
        float* zs  = s_scf;            // 512
        float* red = s_scf + 512;      // [4][128]

        // stage 1: one column per thread, coalesced W1
        {
            float z = 0.0f;
            #pragma unroll 8
            for (int k = 0; k < 128; k++)
                z = fmaf(s_hn2[k], W1[k*DFF + tid], z);
            zs[tid] = fmaxf(z + bf1[tid], 0.0f);
        }
        __syncthreads();

        // stage 2: 4-way k-split, coalesced W2
        {
            int part = tid >> 7, d = tid & 127;
            int j0 = part * 128;
            float o0 = 0.f, o1 = 0.f;
            #pragma unroll 4
            for (int jj = 0; jj < 128; jj += 2){
                o0 = fmaf(zs[j0+jj],   W2[(j0+jj)*DD + d],   o0);
                o1 = fmaf(zs[j0+jj+1], W2[(j0+jj+1)*DD + d], o1);
            }
            red[part*128 + d] = o0 + o1;
        }
        __syncthreads();
        if (tid < 128)
            out[bid*DD + tid] = s_yrow[tid] + red[tid] + red[128+tid]
                              + red[256+tid] + red[384+tid] + bf2[tid];
    }
}

// ---------------- launch ------------------------------------------------------
extern "C" void kernel_launch(void* const* d_in, const int* in_sizes, int n_in,
                              void* d_out, int out_size)
{
    const float* x      = (const float*)d_in[0];
    const int*   mask   = (const int*)  d_in[1];
    const float* coords = (const float*)d_in[2];
    const float* Wp = (const float*)d_in[3],  *bp  = (const float*)d_in[4];
    const float* Wq = (const float*)d_in[5],  *bq  = (const float*)d_in[6];
    const float* Wk = (const float*)d_in[7],  *bk  = (const float*)d_in[8];
    const float* Wv = (const float*)d_in[9],  *bv  = (const float*)d_in[10];
    const float* Wo = (const float*)d_in[11], *bo  = (const float*)d_in[12];
    const float* g1 = (const float*)d_in[13], *b1  = (const float*)d_in[14];
    const float* g2 = (const float*)d_in[15], *b2  = (const float*)d_in[16];
    const float* W1 = (const float*)d_in[17], *bf1 = (const float*)d_in[18];
    const float* W2 = (const float*)d_in[19], *bf2 = (const float*)d_in[20];
    float* out = (float*)d_out;

    k_fused<<<GRID, TPB>>>(x, mask, coords, Wp, bp, Wq, bq, Wk, bk, Wv, bv,
                           Wo, bo, g1, b1, g2, b2, W1, bf1, W2, bf2, out);
}

// round 9
// speedup vs baseline: 1.4409x; 1.1415x over previous
#include <cuda_runtime.h>
#include <math.h>

#define BB 4
#define NN 32
#define DD 128
#define HH 8
#define NCC 27
#define DFF 512
#define LL (NCC*NN)        // 864
#define NR (BB*NN)         // 128 token rows
#define GRID NR
#define TPB 1024

// ---------------- scratch (static device globals; no allocation) -------------
__device__ float g_mxb[NR], g_ssxb[NR];
__device__ float g_XW[NR*3];
__device__ __align__(16) float g_Xk[NR*DD], g_Xv[NR*DD];
__device__ float g_Mk[3*DD], g_Mv[3*DD];
__device__ float g_uq[DD], g_uk[DD], g_uv[DD];
__device__ float g_cq[DD], g_ck[DD], g_cv[DD];
__device__ float g_G[9], g_rs[3];
__device__ unsigned g_tick;            // monotonic barrier ticket (never reset)

__inline__ __device__ float warpSum(float v){
    #pragma unroll
    for (int o = 16; o; o >>= 1) v += __shfl_down_sync(0xffffffffu, v, o);
    return v;
}

__global__ void __launch_bounds__(TPB, 1)
k_fused(const float* __restrict__ x, const int* __restrict__ mask,
        const float* __restrict__ coords,
        const float* __restrict__ Wp, const float* __restrict__ bp,
        const float* __restrict__ Wq, const float* __restrict__ bq,
        const float* __restrict__ Wk, const float* __restrict__ bk,
        const float* __restrict__ Wv, const float* __restrict__ bv,
        const float* __restrict__ Wo, const float* __restrict__ bo,
        const float* __restrict__ g1, const float* __restrict__ b1,
        const float* __restrict__ g2, const float* __restrict__ b2,
        const float* __restrict__ W1, const float* __restrict__ bf1,
        const float* __restrict__ W2, const float* __restrict__ bf2,
        float* __restrict__ out)
{
    __shared__ float s_sc[HH][LL];          // 27.6 KB, heavily overlaid
    __shared__ float s_mu[LL], s_rstd[LL];  // 6.9 KB
    __shared__ float s_xb[128], s_Xq[128], s_yrow[128], s_hn2[128], s_atts[128];
    __shared__ float s_QXk[HH][32];
    __shared__ float s_qMk[HH][4], s_quk[HH], s_qck[HH];
    __shared__ float s_A[HH][32], s_B[HH][4], s_G8[HH];
    __shared__ float s_Ap[4][HH][32], s_Bp[4][HH][4], s_Gp4[4][HH];
    __shared__ float s_sm[2][HH][2];
    __shared__ float s_mxb[32], s_ssxb[32], s_XW[32][3];
    __shared__ float rsm[4][2], stat[2];
    __shared__ int   mk[32];

    float* s_scf = &s_sc[0][0];
    int bid = blockIdx.x, tid = threadIdx.x;
    int b = bid >> 5, i = bid & 31;
    int lane = tid & 31;

    // ===================== PHASE 1: precomputes ==============================
    {
        float* part  = s_scf;          // 768 (3 matrices x 2 halves x 128)
        float* paux  = s_scf + 768;    // 256
        float* s_xbg = s_scf + 1024;   // 128
        float* s_aux = s_scf + 1152;   // 128

        if (tid < 128){
            float xv = x[bid*DD + tid] + bp[tid];
            s_xb[tid]  = xv;
            s_xbg[tid] = xv * g1[tid];
            float p0 = xv * Wp[tid], p1 = xv * Wp[DD+tid], p2 = xv * Wp[2*DD+tid];
            float s = warpSum(xv), ss = warpSum(xv*xv);
            p0 = warpSum(p0); p1 = warpSum(p1); p2 = warpSum(p2);
            int w = tid >> 5;
            if (lane == 0){
                rsm[w][0] = s; rsm[w][1] = ss;
                s_XW[w][0] = p0; s_XW[w][1] = p1; s_XW[w][2] = p2;  // temp reuse
            }
        } else if (bid < 12 && tid >= 896){
            int t = tid - 896;
            int unit = bid;
            if (unit < 6)      s_aux[t] = Wp[(unit%3)*DD + t] * g1[t];
            else if (unit < 9) s_aux[t] = g1[t];
            else               s_aux[t] = b1[t];
        }
        __syncthreads();

        if (tid == 0){
            g_mxb[bid]  = (rsm[0][0]+rsm[1][0]+rsm[2][0]+rsm[3][0]) * (1.0f/128.0f);
            g_ssxb[bid] =  rsm[0][1]+rsm[1][1]+rsm[2][1]+rsm[3][1];
        } else if (tid < 4){
            g_XW[bid*3 + (tid-1)] = s_XW[0][tid-1]+s_XW[1][tid-1]+s_XW[2][tid-1]+s_XW[3][tid-1];
        }

        if (tid < 768){
            // row GEMMs: 3 matrices x 128 cols x 2 k-halves (64-FMA chains)
            int m = tid >> 8, r = tid & 255;
            int half = r >> 7, j = r & 127, k0 = half*64;
            const float* W = (m==0) ? Wq : ((m==1) ? Wk : Wv);
            float acc = 0.0f;
            #pragma unroll 8
            for (int kk = 0; kk < 64; kk++)
                acc = fmaf(s_xbg[k0+kk], W[(k0+kk)*DD + j], acc);
            part[tid] = acc;
        } else if (bid < 12){
            int t = tid - 768;           // 0..255
            int half = t >> 7, j = t & 127, k0 = half*64;
            int unit = bid;
            const float* W;
            if (unit < 3)       W = Wk;
            else if (unit < 6)  W = Wv;
            else if (unit == 6 || unit == 9)  W = Wq;
            else if (unit == 7 || unit == 10) W = Wk;
            else                W = Wv;
            float acc = 0.0f;
            #pragma unroll 8
            for (int kk = 0; kk < 64; kk++)
                acc = fmaf(s_aux[k0+kk], W[(k0+kk)*DD + j], acc);
            paux[t] = acc;
        } else if (bid == 12 && tid >= 768){
            // G = Wp Wp^T (9), rs (3)
            int w = (tid - 768) >> 5;
            for (int o = w; o < 12; o += 8){
                float acc = 0.0f;
                if (o < 9){
                    int a = o/3, c = o%3;
                    #pragma unroll
                    for (int q4 = 0; q4 < 4; q4++){
                        int k = lane + q4*32;
                        acc = fmaf(Wp[a*DD+k], Wp[c*DD+k], acc);
                    }
                    acc = warpSum(acc);
                    if (lane == 0) g_G[o] = acc;
                } else {
                    int a = o - 9;
                    #pragma unroll
                    for (int q4 = 0; q4 < 4; q4++) acc += Wp[a*DD + lane + q4*32];
                    acc = warpSum(acc);
                    if (lane == 0) g_rs[a] = acc;
                }
            }
        }
        __syncthreads();

        if (tid < 384){
            int m = tid >> 7, j = tid & 127;
            float v = part[m*256 + j] + part[m*256 + 128 + j];
            if      (m == 0) s_Xq[j] = v;
            else if (m == 1) g_Xk[bid*DD + j] = v;
            else             g_Xv[bid*DD + j] = v;
        } else if (bid < 12 && tid >= 384 && tid < 512){
            int j = tid - 384;
            int unit = bid;
            float* O; const float* bias = 0;
            if (unit < 3)      O = g_Mk + unit*DD;
            else if (unit < 6) O = g_Mv + (unit-3)*DD;
            else if (unit == 6) O = g_uq;
            else if (unit == 7) O = g_uk;
            else if (unit == 8) O = g_uv;
            else if (unit == 9){ O = g_cq; bias = bq; }
            else if (unit ==10){ O = g_ck; bias = bk; }
            else               { O = g_cv; bias = bv; }
            O[j] = paux[j] + paux[128+j] + (bias ? bias[j] : 0.0f);
        }
    }

    // ===================== GLOBAL BARRIER (monotonic ticket) ==================
    __syncthreads();
    if (tid == 0){
        __threadfence();
        unsigned my = atomicAdd(&g_tick, 1u);
        unsigned target = (my / GRID + 1u) * GRID;
        while (atomicAdd(&g_tick, 0u) < target) { }
        __threadfence();
    }
    __syncthreads();

    // ===================== PHASE 2: attention (factored) =====================
    const float* cb = coords + b*LL*3;
    {
        float* s_q = s_scf;   // temp overlay until scores are written

        if (tid < 32){
            mk[tid]     = mask[b*32 + tid];
            s_mxb[tid]  = g_mxb[b*32 + tid];
            s_ssxb[tid] = g_ssxb[b*32 + tid];
        }
        if (tid >= 416 && tid < 512){
            int t = tid - 416;
            s_XW[t/3][t%3] = g_XW[b*96 + t];
        }
        if (tid >= 128 && tid < 256){
            int d = tid - 128;
            float mu_i = g_mxb[bid];
            float rstd_i = rsqrtf(g_ssxb[bid]*(1.0f/128.0f) - mu_i*mu_i + 1e-5f);
            s_q[d] = rstd_i*s_Xq[d] - rstd_i*mu_i*g_uq[d] + g_cq[d];
        }
        __syncthreads();

        if (tid < 256){
            int h = tid >> 5, n = tid & 31;
            float acc = 0.0f;
            #pragma unroll
            for (int j = 0; j < 16; j++)
                acc = fmaf(s_q[h*16+j], g_Xk[(b*32+n)*DD + h*16 + j], acc);
            s_QXk[h][n] = acc;
        } else if (tid < 280){
            int t = tid - 256;
            int h = t/3, a = t%3;
            float acc = 0.0f;
            #pragma unroll
            for (int j = 0; j < 16; j++) acc = fmaf(s_q[h*16+j], g_Mk[a*DD + h*16 + j], acc);
            s_qMk[h][a] = acc;
        } else if (tid < 288){
            int h = tid - 280;
            float acc = 0.0f;
            #pragma unroll
            for (int j = 0; j < 16; j++) acc = fmaf(s_q[h*16+j], g_uk[h*16+j], acc);
            s_quk[h] = acc;
        } else if (tid < 296){
            int h = tid - 288;
            float acc = 0.0f;
            #pragma unroll
            for (int j = 0; j < 16; j++) acc = fmaf(s_q[h*16+j], g_ck[h*16+j], acc);
            s_qck[h] = acc;
        }
        __syncthreads();
    }

    // scores + LN stats: one key per thread
    if (tid < LL){
        int l = tid;
        int c = l >> 5, n = l & 31;
        int lb = l*3, ib = (c*32 + i)*3;
        float d0 = cb[lb]   - cb[ib];
        float d1 = cb[lb+1] - cb[ib+1];
        float d2 = cb[lb+2] - cb[ib+2];
        float mu = s_mxb[n] + (d0*g_rs[0] + d1*g_rs[1] + d2*g_rs[2]) * (1.0f/128.0f);
        float ss = s_ssxb[n]
                 + 2.0f*(d0*s_XW[n][0] + d1*s_XW[n][1] + d2*s_XW[n][2])
                 + d0*(g_G[0]*d0 + g_G[1]*d1 + g_G[2]*d2)
                 + d1*(g_G[3]*d0 + g_G[4]*d1 + g_G[5]*d2)
                 + d2*(g_G[6]*d0 + g_G[7]*d1 + g_G[8]*d2);
        float var = ss*(1.0f/128.0f) - mu*mu;
        float rstd = rsqrtf(var + 1e-5f);
        s_mu[l] = mu; s_rstd[l] = rstd;
        float rm = rstd*mu;
        bool msk = (mk[n] == 0);
        #pragma unroll
        for (int h = 0; h < 8; h++){
            float s = rstd*(s_QXk[h][n] + d0*s_qMk[h][0] + d1*s_qMk[h][1] + d2*s_qMk[h][2])
                    - rm*s_quk[h] + s_qck[h];
            s *= 0.25f;
            s_sc[h][l] = msk ? -1e9f : s;
        }
    }
    __syncthreads();

    // softmax: 2 warps per head, online merge
    if (tid < 512){
        int w = tid >> 5;
        int h = w & 7, half = w >> 3;
        int start = half*32 + lane;
        float m = -3.4e38f;
        for (int l = start; l < LL; l += 64) m = fmaxf(m, s_sc[h][l]);
        #pragma unroll
        for (int o = 16; o; o >>= 1) m = fmaxf(m, __shfl_xor_sync(0xffffffffu, m, o));
        float sum = 0.0f;
        for (int l = start; l < LL; l += 64){
            float e = __expf(s_sc[h][l] - m);
            s_sc[h][l] = e;
            sum += e;
        }
        #pragma unroll
        for (int o = 16; o; o >>= 1) sum += __shfl_xor_sync(0xffffffffu, sum, o);
        if (lane == 0){ s_sm[half][h][0] = m; s_sm[half][h][1] = sum; }
        __syncthreads();
        float m0 = s_sm[0][h][0], s0 = s_sm[0][h][1];
        float m1 = s_sm[1][h][0], s1 = s_sm[1][h][1];
        float M = fmaxf(m0, m1);
        float S = s0*__expf(m0 - M) + s1*__expf(m1 - M);
        float scale = __expf((half ? m1 : m0) - M) / S;
        for (int l = start; l < LL; l += 64) s_sc[h][l] *= scale;
    } else {
        __syncthreads();
    }
    __syncthreads();

    // V aggregates: 32 warps = (c-quarter, head)
    {
        int w = tid >> 5, n = lane;
        int h = w & 7, q = w >> 3;
        int c0 = q*7, c1 = (q == 3) ? 27 : c0 + 7;
        float A = 0.f, B0 = 0.f, B1 = 0.f, B2 = 0.f, Gp = 0.f;
        #pragma unroll 1
        for (int c = c0; c < c1; c++){
            int l = c*32 + n;
            float wr = s_sc[h][l] * s_rstd[l];
            int lb = l*3, ib = (c*32 + i)*3;
            float d0 = cb[lb] - cb[ib], d1 = cb[lb+1] - cb[ib+1], d2 = cb[lb+2] - cb[ib+2];
            A += wr;
            B0 = fmaf(wr, d0, B0); B1 = fmaf(wr, d1, B1); B2 = fmaf(wr, d2, B2);
            Gp = fmaf(-wr, s_mu[l], Gp);
        }
        s_Ap[q][h][n] = A;
        B0 = warpSum(B0); B1 = warpSum(B1); B2 = warpSum(B2); Gp = warpSum(Gp);
        if (n == 0){
            s_Bp[q][h][0]=B0; s_Bp[q][h][1]=B1; s_Bp[q][h][2]=B2; s_Gp4[q][h]=Gp;
        }
    }
    __syncthreads();
    if (tid < 256){
        int h = tid >> 5, n = tid & 31;
        s_A[h][n] = s_Ap[0][h][n] + s_Ap[1][h][n] + s_Ap[2][h][n] + s_Ap[3][h][n];
    } else if (tid < 280){
        int t = tid - 256;
        int h = t/3, a = t%3;
        s_B[h][a] = s_Bp[0][h][a] + s_Bp[1][h][a] + s_Bp[2][h][a] + s_Bp[3][h][a];
    } else if (tid < 288){
        int h = tid - 280;
        s_G8[h] = s_Gp4[0][h] + s_Gp4[1][h] + s_Gp4[2][h] + s_Gp4[3][h];
    }
    __syncthreads();

    // scores no longer needed -> overlay partial buffers on s_sc
    {
        float* pa  = s_scf;            // 256 (atts partials)
        float* red = s_scf + 1024;     // 1024 (Wo partials)

        if (tid < 256){
            int d = tid & 127, nh = tid >> 7;
            int h = d >> 4;
            float acc;
            if (nh == 0){
                acc = g_cv[d] + s_G8[h]*g_uv[d]
                    + s_B[h][0]*g_Mv[d] + s_B[h][1]*g_Mv[DD+d] + s_B[h][2]*g_Mv[2*DD+d];
            } else acc = 0.0f;
            const float* Xvb = g_Xv + b*32*DD;
            int n0 = nh*16;
            #pragma unroll
            for (int n = 0; n < 16; n++) acc = fmaf(s_A[h][n0+n], Xvb[(n0+n)*DD + d], acc);
            pa[nh*128 + d] = acc;
        }
        __syncthreads();
        if (tid < 128) s_atts[tid] = pa[tid] + pa[128+tid];
        __syncthreads();

        // Wo projection: 8-way k-split (16-FMA chains)
        {
            int part = tid >> 7, dp = tid & 127;
            float o = 0.0f;
            int k0 = part*16;
            #pragma unroll
            for (int k = 0; k < 16; k++) o = fmaf(s_atts[k0+k], Wo[(k0+k)*DD + dp], o);
            red[part*128 + dp] = o;
        }
        __syncthreads();
        if (tid < 128){
            float y = s_xb[tid] + bo[tid]
                    + red[tid] + red[128+tid] + red[256+tid] + red[384+tid]
                    + red[512+tid] + red[640+tid] + red[768+tid] + red[896+tid];
            s_yrow[tid] = y;
            float s = warpSum(y), s2 = warpSum(y*y);
            if (lane == 0){ rsm[tid>>5][0] = s; rsm[tid>>5][1] = s2; }
        }
        __syncthreads();
        if (tid == 0){
            float s  = rsm[0][0]+rsm[1][0]+rsm[2][0]+rsm[3][0];
            float s2 = rsm[0][1]+rsm[1][1]+rsm[2][1]+rsm[3][1];
            float m = s * (1.0f/128.0f);
            stat[0] = m;
            stat[1] = rsqrtf(s2*(1.0f/128.0f) - m*m + 1e-5f);
        }
        __syncthreads();
        if (tid < 128)
            s_hn2[tid] = (s_yrow[tid] - stat[0])*stat[1]*g2[tid] + b2[tid];
        __syncthreads();
    }

    // ===================== PHASE 3: FFN (same row, no barrier) ================
    {
        float* zp  = s_scf;            // 1024 (stage-1 partials)
        float* zs  = s_scf + 1024;     // 512
        float* red = s_scf + 1536;     // 1024

        // stage 1: col x 2 k-halves (64-FMA chains)
        {
            int col = tid & 511, half = tid >> 9;
            int k0 = half*64;
            float z = 0.0f;
            #pragma unroll 8
            for (int kk = 0; kk < 64; kk++)
                z = fmaf(s_hn2[k0+kk], W1[(k0+kk)*DFF + col], z);
            zp[half*512 + col] = z;
        }
        __syncthreads();
        if (tid < 512)
            zs[tid] = fmaxf(zp[tid] + zp[512+tid] + bf1[tid], 0.0f);
        __syncthreads();

        // stage 2: 8-way k-split, dual accumulators (32-dep chains)
        {
            int part = tid >> 7, d = tid & 127;
            int j0 = part * 64;
            float o0 = 0.f, o1 = 0.f;
            #pragma unroll 4
            for (int jj = 0; jj < 64; jj += 2){
                o0 = fmaf(zs[j0+jj],   W2[(j0+jj)*DD + d],   o0);
                o1 = fmaf(zs[j0+jj+1], W2[(j0+jj+1)*DD + d], o1);
            }
            red[part*128 + d] = o0 + o1;
        }
        __syncthreads();
        if (tid < 128)
            out[bid*DD + tid] = s_yrow[tid] + bf2[tid]
                              + red[tid] + red[128+tid] + red[256+tid] + red[384+tid]
                              + red[512+tid] + red[640+tid] + red[768+tid] + red[896+tid];
    }
}

// ---------------- launch ------------------------------------------------------
extern "C" void kernel_launch(void* const* d_in, const int* in_sizes, int n_in,
                              void* d_out, int out_size)
{
    const float* x      = (const float*)d_in[0];
    const int*   mask   = (const int*)  d_in[1];
    const float* coords = (const float*)d_in[2];
    const float* Wp = (const float*)d_in[3],  *bp  = (const float*)d_in[4];
    const float* Wq = (const float*)d_in[5],  *bq  = (const float*)d_in[6];
    const float* Wk = (const float*)d_in[7],  *bk  = (const float*)d_in[8];
    const float* Wv = (const float*)d_in[9],  *bv  = (const float*)d_in[10];
    const float* Wo = (const float*)d_in[11], *bo  = (const float*)d_in[12];
    const float* g1 = (const float*)d_in[13], *b1  = (const float*)d_in[14];
    const float* g2 = (const float*)d_in[15], *b2  = (const float*)d_in[16];
    const float* W1 = (const float*)d_in[17], *bf1 = (const float*)d_in[18];
    const float* W2 = (const float*)d_in[19], *bf2 = (const float*)d_in[20];
    float* out = (float*)d_out;

    k_fused<<<GRID, TPB>>>(x, mask, coords, Wp, bp, Wq, bq, Wk, bk, Wv, bv,
                           Wo, bo, g1, b1, g2, b2, W1, bf1, W2, bf2, out);
}

// round 10
// speedup vs baseline: 1.7450x; 1.2110x over previous
#include <cuda_runtime.h>
#include <math.h>

#define BB 4
#define NN 32
#define DD 128
#define HH 8
#define NCC 27
#define DFF 512
#define LL (NCC*NN)        // 864
#define NR (BB*NN)         // 128 token rows
#define GRID NR
#define TPB 1024

// ---------------- scratch (static device globals; no allocation) -------------
__device__ float g_mxb[NR], g_ssxb[NR];
__device__ float g_XW[NR*3];
__device__ __align__(16) float g_Xk[NR*DD], g_Xv[NR*DD];
__device__ __align__(16) float g_Mv[3*DD];
__device__ float g_Mk[3*DD];
__device__ float g_uq[DD], g_uk[DD], g_uv[DD];
__device__ float g_cq[DD], g_ck[DD], g_cv[DD];
__device__ float g_G[9], g_rs[3];
__device__ unsigned g_tick;            // monotonic barrier ticket (never reset)

__inline__ __device__ float warpSum(float v){
    #pragma unroll
    for (int o = 16; o; o >>= 1) v += __shfl_down_sync(0xffffffffu, v, o);
    return v;
}

__global__ void __launch_bounds__(TPB, 1)
k_fused(const float* __restrict__ x, const int* __restrict__ mask,
        const float* __restrict__ coords,
        const float* __restrict__ Wp, const float* __restrict__ bp,
        const float* __restrict__ Wq, const float* __restrict__ bq,
        const float* __restrict__ Wk, const float* __restrict__ bk,
        const float* __restrict__ Wv, const float* __restrict__ bv,
        const float* __restrict__ Wo, const float* __restrict__ bo,
        const float* __restrict__ g1, const float* __restrict__ b1,
        const float* __restrict__ g2, const float* __restrict__ b2,
        const float* __restrict__ W1, const float* __restrict__ bf1,
        const float* __restrict__ W2, const float* __restrict__ bf2,
        float* __restrict__ out)
{
    // big overlay buffer (= 8*864 floats, 27.6 KB), phase-specific layouts
    __shared__ __align__(16) float s_buf[HH*LL];
    __shared__ float s_mu[LL], s_rstd[LL];
    __shared__ float s_xb[128], s_Xq[128], s_yrow[128], s_hn2[128], s_atts[128];
    __shared__ float s_QXk[HH][32];
    __shared__ float s_qMk[HH][4], s_quk[HH], s_qck[HH];
    __shared__ float s_A[HH][32], s_B[HH][4], s_G8[HH];
    __shared__ float s_Ap[4][HH][32], s_Bp[4][HH][4], s_Gp4[4][HH];
    __shared__ float s_sm4[4][HH][2];
    __shared__ float s_mxb[32], s_ssxb[32], s_XW[32][3];
    __shared__ float rsm[4][2], stat[2];
    __shared__ int   mk[32];

    int bid = blockIdx.x, tid = threadIdx.x;
    int b = bid >> 5, i = bid & 31;
    int lane = tid & 31;

    // ===================== PHASE 1: precomputes ==============================
    {
        float* part  = s_buf;          // 3*8*128 = 3072
        float* paux  = s_buf + 3072;   // 8*128 = 1024
        float* s_xbg = s_buf + 4096;   // 128
        float* s_aux = s_buf + 4224;   // 128

        if (tid < 128){
            float xv = x[bid*DD + tid] + bp[tid];
            s_xb[tid]  = xv;
            s_xbg[tid] = xv * g1[tid];
            float p0 = xv * Wp[tid], p1 = xv * Wp[DD+tid], p2 = xv * Wp[2*DD+tid];
            float s = warpSum(xv), ss = warpSum(xv*xv);
            p0 = warpSum(p0); p1 = warpSum(p1); p2 = warpSum(p2);
            int w = tid >> 5;
            if (lane == 0){
                rsm[w][0] = s; rsm[w][1] = ss;
                s_XW[w][0] = p0; s_XW[w][1] = p1; s_XW[w][2] = p2;  // temp reuse
            }
        } else if (bid < 12 && tid >= 896){
            int t = tid - 896;
            int unit = bid;
            if (unit < 6)      s_aux[t] = Wp[(unit%3)*DD + t] * g1[t];
            else if (unit < 9) s_aux[t] = g1[t];
            else               s_aux[t] = b1[t];
        }
        __syncthreads();

        if (tid == 0){
            g_mxb[bid]  = (rsm[0][0]+rsm[1][0]+rsm[2][0]+rsm[3][0]) * (1.0f/128.0f);
            g_ssxb[bid] =  rsm[0][1]+rsm[1][1]+rsm[2][1]+rsm[3][1];
        } else if (tid < 4){
            g_XW[bid*3 + (tid-1)] = s_XW[0][tid-1]+s_XW[1][tid-1]+s_XW[2][tid-1]+s_XW[3][tid-1];
        }

        if (tid < 768){
            // row GEMMs: 3 matrices x 32 col-quads x 8 k-octants, float4 loads
            int m = tid >> 8, r = tid & 255;
            int cg = r & 31, ko = r >> 5;
            int k0 = ko*16, j4 = cg*4;
            const float* W = (m==0) ? Wq : ((m==1) ? Wk : Wv);
            float a0=0.f, a1=0.f, a2=0.f, a3=0.f;
            #pragma unroll 4
            for (int kk = 0; kk < 16; kk++){
                float a = s_xbg[k0+kk];
                float4 w = *(const float4*)&W[(k0+kk)*DD + j4];
                a0 = fmaf(a, w.x, a0); a1 = fmaf(a, w.y, a1);
                a2 = fmaf(a, w.z, a2); a3 = fmaf(a, w.w, a3);
            }
            float4 o; o.x=a0; o.y=a1; o.z=a2; o.w=a3;
            *(float4*)&part[m*1024 + ko*128 + j4] = o;
        } else if (bid < 12){
            // aux unit GEMM: 32 col-quads x 8 k-octants on threads 768..1023
            int t = tid - 768;
            int cg = t & 31, ko = t >> 5;
            int k0 = ko*16, j4 = cg*4;
            int unit = bid;
            const float* W;
            if (unit < 3)       W = Wk;
            else if (unit < 6)  W = Wv;
            else if (unit == 6 || unit == 9)  W = Wq;
            else if (unit == 7 || unit == 10) W = Wk;
            else                W = Wv;
            float a0=0.f, a1=0.f, a2=0.f, a3=0.f;
            #pragma unroll 4
            for (int kk = 0; kk < 16; kk++){
                float a = s_aux[k0+kk];
                float4 w = *(const float4*)&W[(k0+kk)*DD + j4];
                a0 = fmaf(a, w.x, a0); a1 = fmaf(a, w.y, a1);
                a2 = fmaf(a, w.z, a2); a3 = fmaf(a, w.w, a3);
            }
            float4 o; o.x=a0; o.y=a1; o.z=a2; o.w=a3;
            *(float4*)&paux[ko*128 + j4] = o;
        } else if (bid == 12 && tid >= 768){
            // G = Wp Wp^T (9), rs (3)
            int w = (tid - 768) >> 5;
            for (int o = w; o < 12; o += 8){
                float acc = 0.0f;
                if (o < 9){
                    int a = o/3, c = o%3;
                    #pragma unroll
                    for (int q4 = 0; q4 < 4; q4++){
                        int k = lane + q4*32;
                        acc = fmaf(Wp[a*DD+k], Wp[c*DD+k], acc);
                    }
                    acc = warpSum(acc);
                    if (lane == 0) g_G[o] = acc;
                } else {
                    int a = o - 9;
                    #pragma unroll
                    for (int q4 = 0; q4 < 4; q4++) acc += Wp[a*DD + lane + q4*32];
                    acc = warpSum(acc);
                    if (lane == 0) g_rs[a] = acc;
                }
            }
        }
        __syncthreads();

        if (tid < 384){
            int m = tid >> 7, j = tid & 127;
            const float* pm = part + m*1024;
            float v = pm[j] + pm[128+j] + pm[256+j] + pm[384+j]
                    + pm[512+j] + pm[640+j] + pm[768+j] + pm[896+j];
            if      (m == 0) s_Xq[j] = v;
            else if (m == 1) g_Xk[bid*DD + j] = v;
            else             g_Xv[bid*DD + j] = v;
        } else if (bid < 12 && tid >= 384 && tid < 512){
            int j = tid - 384;
            int unit = bid;
            float* O; const float* bias = 0;
            if (unit < 3)      O = g_Mk + unit*DD;
            else if (unit < 6) O = g_Mv + (unit-3)*DD;
            else if (unit == 6) O = g_uq;
            else if (unit == 7) O = g_uk;
            else if (unit == 8) O = g_uv;
            else if (unit == 9){ O = g_cq; bias = bq; }
            else if (unit ==10){ O = g_ck; bias = bk; }
            else               { O = g_cv; bias = bv; }
            float v = paux[j] + paux[128+j] + paux[256+j] + paux[384+j]
                    + paux[512+j] + paux[640+j] + paux[768+j] + paux[896+j];
            O[j] = v + (bias ? bias[j] : 0.0f);
        }
    }

    // ===================== GLOBAL BARRIER (ticket + volatile spin) ============
    __syncthreads();
    if (tid == 0){
        __threadfence();
        unsigned my = atomicAdd(&g_tick, 1u);
        unsigned target = (my / GRID + 1u) * GRID;
        volatile unsigned* vt = &g_tick;
        while (*vt < target) { }
        __threadfence();
    }
    __syncthreads();

    // ===================== PHASE 2: attention (factored) =====================
    const float* cb = coords + b*LL*3;
    {
        float* s_q = s_buf;   // temp overlay until scores are written

        if (tid < 32){
            mk[tid]     = mask[b*32 + tid];
            s_mxb[tid]  = g_mxb[b*32 + tid];
            s_ssxb[tid] = g_ssxb[b*32 + tid];
        }
        if (tid >= 416 && tid < 512){
            int t = tid - 416;
            s_XW[t/3][t%3] = g_XW[b*96 + t];
        }
        if (tid >= 128 && tid < 256){
            int d = tid - 128;
            float mu_i = g_mxb[bid];
            float rstd_i = rsqrtf(g_ssxb[bid]*(1.0f/128.0f) - mu_i*mu_i + 1e-5f);
            s_q[d] = rstd_i*s_Xq[d] - rstd_i*mu_i*g_uq[d] + g_cq[d];
        }
        __syncthreads();

        if (tid < 256){
            int h = tid >> 5, n = tid & 31;
            const float4* q4 = (const float4*)&s_q[h*16];
            const float4* k4 = (const float4*)&g_Xk[(b*32+n)*DD + h*16];
            float acc = 0.0f;
            #pragma unroll
            for (int j = 0; j < 4; j++){
                float4 qq = q4[j], kk = k4[j];
                acc = fmaf(qq.x, kk.x, fmaf(qq.y, kk.y,
                      fmaf(qq.z, kk.z, fmaf(qq.w, kk.w, acc))));
            }
            s_QXk[h][n] = acc;
        } else if (tid < 280){
            int t = tid - 256;
            int h = t/3, a = t%3;
            float acc = 0.0f;
            #pragma unroll
            for (int j = 0; j < 16; j++) acc = fmaf(s_q[h*16+j], g_Mk[a*DD + h*16 + j], acc);
            s_qMk[h][a] = acc;
        } else if (tid < 288){
            int h = tid - 280;
            float acc = 0.0f;
            #pragma unroll
            for (int j = 0; j < 16; j++) acc = fmaf(s_q[h*16+j], g_uk[h*16+j], acc);
            s_quk[h] = acc;
        } else if (tid < 296){
            int h = tid - 288;
            float acc = 0.0f;
            #pragma unroll
            for (int j = 0; j < 16; j++) acc = fmaf(s_q[h*16+j], g_ck[h*16+j], acc);
            s_qck[h] = acc;
        }
        __syncthreads();
    }

    // scores + LN stats: one key per thread (s_buf becomes scores [h][l])
    if (tid < LL){
        int l = tid;
        int c = l >> 5, n = l & 31;
        int lb = l*3, ib = (c*32 + i)*3;
        float d0 = cb[lb]   - cb[ib];
        float d1 = cb[lb+1] - cb[ib+1];
        float d2 = cb[lb+2] - cb[ib+2];
        float mu = s_mxb[n] + (d0*g_rs[0] + d1*g_rs[1] + d2*g_rs[2]) * (1.0f/128.0f);
        float ss = s_ssxb[n]
                 + 2.0f*(d0*s_XW[n][0] + d1*s_XW[n][1] + d2*s_XW[n][2])
                 + d0*(g_G[0]*d0 + g_G[1]*d1 + g_G[2]*d2)
                 + d1*(g_G[3]*d0 + g_G[4]*d1 + g_G[5]*d2)
                 + d2*(g_G[6]*d0 + g_G[7]*d1 + g_G[8]*d2);
        float var = ss*(1.0f/128.0f) - mu*mu;
        float rstd = rsqrtf(var + 1e-5f);
        s_mu[l] = mu; s_rstd[l] = rstd;
        float rm = rstd*mu;
        bool msk = (mk[n] == 0);
        #pragma unroll
        for (int h = 0; h < 8; h++){
            float s = rstd*(s_QXk[h][n] + d0*s_qMk[h][0] + d1*s_qMk[h][1] + d2*s_qMk[h][2])
                    - rm*s_quk[h] + s_qck[h];
            s *= 0.25f;
            s_buf[h*LL + l] = msk ? -1e9f : s;
        }
    }
    __syncthreads();

    // softmax: 4 warps per head, online merge
    {
        int w = tid >> 5;
        int h = w & 7, q = w >> 3;
        int start = q*32 + lane;
        float* sch = s_buf + h*LL;
        float m = -3.4e38f;
        for (int l = start; l < LL; l += 128) m = fmaxf(m, sch[l]);
        #pragma unroll
        for (int o = 16; o; o >>= 1) m = fmaxf(m, __shfl_xor_sync(0xffffffffu, m, o));
        float sum = 0.0f;
        for (int l = start; l < LL; l += 128){
            float e = __expf(sch[l] - m);
            sch[l] = e;
            sum += e;
        }
        #pragma unroll
        for (int o = 16; o; o >>= 1) sum += __shfl_xor_sync(0xffffffffu, sum, o);
        if (lane == 0){ s_sm4[q][h][0] = m; s_sm4[q][h][1] = sum; }
        __syncthreads();
        float m0 = s_sm4[0][h][0], m1 = s_sm4[1][h][0];
        float m2 = s_sm4[2][h][0], m3 = s_sm4[3][h][0];
        float M = fmaxf(fmaxf(m0, m1), fmaxf(m2, m3));
        float S = s_sm4[0][h][1]*__expf(m0 - M) + s_sm4[1][h][1]*__expf(m1 - M)
                + s_sm4[2][h][1]*__expf(m2 - M) + s_sm4[3][h][1]*__expf(m3 - M);
        float scale = __expf(s_sm4[q][h][0] - M) / S;
        for (int l = start; l < LL; l += 128) sch[l] *= scale;
    }
    __syncthreads();

    // V aggregates: 32 warps = (c-quarter, head)
    {
        int w = tid >> 5, n = lane;
        int h = w & 7, q = w >> 3;
        int c0 = q*7, c1 = (q == 3) ? 27 : c0 + 7;
        const float* sch = s_buf + h*LL;
        float A = 0.f, B0 = 0.f, B1 = 0.f, B2 = 0.f, Gp = 0.f;
        #pragma unroll 1
        for (int c = c0; c < c1; c++){
            int l = c*32 + n;
            float wr = sch[l] * s_rstd[l];
            int lb = l*3, ib = (c*32 + i)*3;
            float d0 = cb[lb] - cb[ib], d1 = cb[lb+1] - cb[ib+1], d2 = cb[lb+2] - cb[ib+2];
            A += wr;
            B0 = fmaf(wr, d0, B0); B1 = fmaf(wr, d1, B1); B2 = fmaf(wr, d2, B2);
            Gp = fmaf(-wr, s_mu[l], Gp);
        }
        s_Ap[q][h][n] = A;
        B0 = warpSum(B0); B1 = warpSum(B1); B2 = warpSum(B2); Gp = warpSum(Gp);
        if (n == 0){
            s_Bp[q][h][0]=B0; s_Bp[q][h][1]=B1; s_Bp[q][h][2]=B2; s_Gp4[q][h]=Gp;
        }
    }
    __syncthreads();
    if (tid < 256){
        int h = tid >> 5, n = tid & 31;
        s_A[h][n] = s_Ap[0][h][n] + s_Ap[1][h][n] + s_Ap[2][h][n] + s_Ap[3][h][n];
    } else if (tid < 280){
        int t = tid - 256;
        int h = t/3, a = t%3;
        s_B[h][a] = s_Bp[0][h][a] + s_Bp[1][h][a] + s_Bp[2][h][a] + s_Bp[3][h][a];
    } else if (tid < 288){
        int h = tid - 280;
        s_G8[h] = s_Gp4[0][h] + s_Gp4[1][h] + s_Gp4[2][h] + s_Gp4[3][h];
    }
    __syncthreads();

    // atts: n-split 8 (4-iter chains), then Wo (float4, 32-way k-split)
    {
        float* pa = s_buf;             // 1024 partials

        {
            int d = tid & 127, nh = tid >> 7;
            int h = d >> 4;
            float acc;
            if (nh == 0){
                acc = g_cv[d] + s_G8[h]*g_uv[d]
                    + s_B[h][0]*g_Mv[d] + s_B[h][1]*g_Mv[DD+d] + s_B[h][2]*g_Mv[2*DD+d];
            } else acc = 0.0f;
            const float* Xvb = g_Xv + b*32*DD;
            int n0 = nh*4;
            #pragma unroll
            for (int n = 0; n < 4; n++) acc = fmaf(s_A[h][n0+n], Xvb[(n0+n)*DD + d], acc);
            pa[nh*128 + d] = acc;
        }
        __syncthreads();
        if (tid < 128)
            s_atts[tid] = pa[tid] + pa[128+tid] + pa[256+tid] + pa[384+tid]
                        + pa[512+tid] + pa[640+tid] + pa[768+tid] + pa[896+tid];
        __syncthreads();

        // Wo: 32 col-quads x 32 k-splits (4 k each), float4 loads
        float* red  = s_buf;           // 4096
        float* red2 = s_buf + 4096;    // 512
        {
            int cg = tid & 31, ks = tid >> 5;
            int k0 = ks*4, j4 = cg*4;
            float a0=0.f, a1=0.f, a2=0.f, a3=0.f;
            #pragma unroll
            for (int kk = 0; kk < 4; kk++){
                float a = s_atts[k0+kk];
                float4 w = *(const float4*)&Wo[(k0+kk)*DD + j4];
                a0 = fmaf(a, w.x, a0); a1 = fmaf(a, w.y, a1);
                a2 = fmaf(a, w.z, a2); a3 = fmaf(a, w.w, a3);
            }
            float4 o; o.x=a0; o.y=a1; o.z=a2; o.w=a3;
            *(float4*)&red[ks*128 + j4] = o;
        }
        __syncthreads();
        if (tid < 512){
            int j = tid & 127, g = tid >> 7;
            float v = 0.0f;
            #pragma unroll
            for (int t = 0; t < 8; t++) v += red[(g + 4*t)*128 + j];
            red2[g*128 + j] = v;
        }
        __syncthreads();
        if (tid < 128){
            float y = s_xb[tid] + bo[tid]
                    + red2[tid] + red2[128+tid] + red2[256+tid] + red2[384+tid];
            s_yrow[tid] = y;
            float s = warpSum(y), s2 = warpSum(y*y);
            if (lane == 0){ rsm[tid>>5][0] = s; rsm[tid>>5][1] = s2; }
        }
        __syncthreads();
        if (tid == 0){
            float s  = rsm[0][0]+rsm[1][0]+rsm[2][0]+rsm[3][0];
            float s2 = rsm[0][1]+rsm[1][1]+rsm[2][1]+rsm[3][1];
            float m = s * (1.0f/128.0f);
            stat[0] = m;
            stat[1] = rsqrtf(s2*(1.0f/128.0f) - m*m + 1e-5f);
        }
        __syncthreads();
        if (tid < 128)
            s_hn2[tid] = (s_yrow[tid] - stat[0])*stat[1]*g2[tid] + b2[tid];
        __syncthreads();
    }

    // ===================== PHASE 3: FFN (float4, deep k-splits) ===============
    {
        float* zp = s_buf;             // 8*512 = 4096 partials
        float* zs = s_buf + 4096;      // 512

        // stage 1: 128 col-quads x 8 k-octants
        {
            int cg = tid & 127, ko = tid >> 7;
            int k0 = ko*16, j4 = cg*4;
            float a0=0.f, a1=0.f, a2=0.f, a3=0.f;
            #pragma unroll 4
            for (int kk = 0; kk < 16; kk++){
                float a = s_hn2[k0+kk];
                float4 w = *(const float4*)&W1[(k0+kk)*DFF + j4];
                a0 = fmaf(a, w.x, a0); a1 = fmaf(a, w.y, a1);
                a2 = fmaf(a, w.z, a2); a3 = fmaf(a, w.w, a3);
            }
            float4 o; o.x=a0; o.y=a1; o.z=a2; o.w=a3;
            *(float4*)&zp[ko*512 + j4] = o;
        }
        __syncthreads();
        if (tid < 512){
            float v = zp[tid] + zp[512+tid] + zp[1024+tid] + zp[1536+tid]
                    + zp[2048+tid] + zp[2560+tid] + zp[3072+tid] + zp[3584+tid];
            zs[tid] = fmaxf(v + bf1[tid], 0.0f);
        }
        __syncthreads();

        // stage 2: 32 col-quads x 32 k-splits (16 k each)
        float* red  = s_buf;           // 4096 (zp region reused)
        float* red2 = s_buf + 4608;    // 512
        {
            int cg = tid & 31, ks = tid >> 5;
            int k0 = ks*16, j4 = cg*4;
            float a0=0.f, a1=0.f, a2=0.f, a3=0.f;
            #pragma unroll 4
            for (int kk = 0; kk < 16; kk++){
                float a = zs[k0+kk];
                float4 w = *(const float4*)&W2[(k0+kk)*DD + j4];
                a0 = fmaf(a, w.x, a0); a1 = fmaf(a, w.y, a1);
                a2 = fmaf(a, w.z, a2); a3 = fmaf(a, w.w, a3);
            }
            float4 o; o.x=a0; o.y=a1; o.z=a2; o.w=a3;
            *(float4*)&red[ks*128 + j4] = o;
        }
        __syncthreads();
        if (tid < 512){
            int j = tid & 127, g = tid >> 7;
            float v = 0.0f;
            #pragma unroll
            for (int t = 0; t < 8; t++) v += red[(g + 4*t)*128 + j];
            red2[g*128 + j] = v;
        }
        __syncthreads();
        if (tid < 128)
            out[bid*DD + tid] = s_yrow[tid] + bf2[tid]
                              + red2[tid] + red2[128+tid] + red2[256+tid] + red2[384+tid];
    }
}

// ---------------- launch ------------------------------------------------------
extern "C" void kernel_launch(void* const* d_in, const int* in_sizes, int n_in,
                              void* d_out, int out_size)
{
    const float* x      = (const float*)d_in[0];
    const int*   mask   = (const int*)  d_in[1];
    const float* coords = (const float*)d_in[2];
    const float* Wp = (const float*)d_in[3],  *bp  = (const float*)d_in[4];
    const float* Wq = (const float*)d_in[5],  *bq  = (const float*)d_in[6];
    const float* Wk = (const float*)d_in[7],  *bk  = (const float*)d_in[8];
    const float* Wv = (const float*)d_in[9],  *bv  = (const float*)d_in[10];
    const float* Wo = (const float*)d_in[11], *bo  = (const float*)d_in[12];
    const float* g1 = (const float*)d_in[13], *b1  = (const float*)d_in[14];
    const float* g2 = (const float*)d_in[15], *b2  = (const float*)d_in[16];
    const float* W1 = (const float*)d_in[17], *bf1 = (const float*)d_in[18];
    const float* W2 = (const float*)d_in[19], *bf2 = (const float*)d_in[20];
    float* out = (float*)d_out;

    k_fused<<<GRID, TPB>>>(x, mask, coords, Wp, bp, Wq, bq, Wk, bk, Wv, bv,
                           Wo, bo, g1, b1, g2, b2, W1, bf1, W2, bf2, out);
}

// round 11
// speedup vs baseline: 1.8610x; 1.0665x over previous
#include <cuda_runtime.h>
#include <math.h>

#define BB 4
#define NN 32
#define DD 128
#define HH 8
#define NCC 27
#define DFF 512
#define LL (NCC*NN)        // 864
#define NR (BB*NN)         // 128 token rows
#define GRID NR
#define TPB 1024

// ---------------- scratch (static device globals; no allocation) -------------
__device__ float g_mxb[NR], g_ssxb[NR];
__device__ float g_XW[NR*3];
__device__ __align__(16) float g_Xk[NR*DD], g_Xv[NR*DD];
__device__ __align__(16) float g_Mv[3*DD];
__device__ float g_Mk[3*DD];
__device__ float g_uq[DD], g_uk[DD], g_uv[DD];
__device__ float g_cq[DD], g_ck[DD], g_cv[DD];
__device__ float g_G[9], g_rs[3];
__device__ unsigned g_tick;            // monotonic barrier ticket (never reset)

__inline__ __device__ float warpSum(float v){
    #pragma unroll
    for (int o = 16; o; o >>= 1) v += __shfl_down_sync(0xffffffffu, v, o);
    return v;
}

__global__ void __launch_bounds__(TPB, 1)
k_fused(const float* __restrict__ x, const int* __restrict__ mask,
        const float* __restrict__ coords,
        const float* __restrict__ Wp, const float* __restrict__ bp,
        const float* __restrict__ Wq, const float* __restrict__ bq,
        const float* __restrict__ Wk, const float* __restrict__ bk,
        const float* __restrict__ Wv, const float* __restrict__ bv,
        const float* __restrict__ Wo, const float* __restrict__ bo,
        const float* __restrict__ g1, const float* __restrict__ b1,
        const float* __restrict__ g2, const float* __restrict__ b2,
        const float* __restrict__ W1, const float* __restrict__ bf1,
        const float* __restrict__ W2, const float* __restrict__ bf2,
        float* __restrict__ out)
{
    // big overlay buffer (= 8*864 floats, 27.6 KB), phase-specific layouts
    __shared__ __align__(16) float s_buf[HH*LL];
    __shared__ float s_mu[LL], s_rstd[LL];
    __shared__ float s_dc0[LL], s_dc1[LL], s_dc2[LL];   // cached coord deltas
    __shared__ float s_xb[128], s_Xq[128], s_yrow[128], s_hn2[128], s_atts[128];
    __shared__ float s_QXk[HH][32];
    __shared__ float s_qMk[HH][4], s_quk[HH], s_qck[HH];
    __shared__ float s_A[HH][32], s_B[HH][4], s_G8[HH];
    __shared__ float s_Ap[4][HH][32], s_Bp[4][HH][4], s_Gp4[4][HH];
    __shared__ float s_sm4[4][HH][2];
    __shared__ float s_scaleq[4][HH];
    __shared__ float s_mxb[32], s_ssxb[32], s_XW[32][3];
    __shared__ float rsm[4][2], stat[2];
    __shared__ int   mk[32];

    int bid = blockIdx.x, tid = threadIdx.x;
    int b = bid >> 5, i = bid & 31;
    int lane = tid & 31;

    // ===================== PHASE 1: precomputes ==============================
    {
        float* part  = s_buf;          // 3*8*128 = 3072
        float* paux  = s_buf + 3072;   // 8*128 = 1024
        float* s_xbg = s_buf + 4096;   // 128
        float* s_aux = s_buf + 4224;   // 128

        if (tid < 128){
            float xv = x[bid*DD + tid] + bp[tid];
            s_xb[tid]  = xv;
            s_xbg[tid] = xv * g1[tid];
            float p0 = xv * Wp[tid], p1 = xv * Wp[DD+tid], p2 = xv * Wp[2*DD+tid];
            float s = warpSum(xv), ss = warpSum(xv*xv);
            p0 = warpSum(p0); p1 = warpSum(p1); p2 = warpSum(p2);
            int w = tid >> 5;
            if (lane == 0){
                rsm[w][0] = s; rsm[w][1] = ss;
                s_XW[w][0] = p0; s_XW[w][1] = p1; s_XW[w][2] = p2;  // temp reuse
            }
        } else if (bid < 12 && tid >= 896){
            int t = tid - 896;
            int unit = bid;
            if (unit < 6)      s_aux[t] = Wp[(unit%3)*DD + t] * g1[t];
            else if (unit < 9) s_aux[t] = g1[t];
            else               s_aux[t] = b1[t];
        }
        __syncthreads();

        if (tid == 0){
            g_mxb[bid]  = (rsm[0][0]+rsm[1][0]+rsm[2][0]+rsm[3][0]) * (1.0f/128.0f);
            g_ssxb[bid] =  rsm[0][1]+rsm[1][1]+rsm[2][1]+rsm[3][1];
        } else if (tid < 4){
            g_XW[bid*3 + (tid-1)] = s_XW[0][tid-1]+s_XW[1][tid-1]+s_XW[2][tid-1]+s_XW[3][tid-1];
        }

        if (tid < 768){
            // row GEMMs: 3 matrices x 32 col-quads x 8 k-octants, float4, full MLP
            int m = tid >> 8, r = tid & 255;
            int cg = r & 31, ko = r >> 5;
            int k0 = ko*16, j4 = cg*4;
            const float* W = (m==0) ? Wq : ((m==1) ? Wk : Wv);
            const float* Wb = W + k0*DD + j4;
            float a0=0.f, a1=0.f, a2=0.f, a3=0.f;
            #pragma unroll
            for (int kk = 0; kk < 16; kk++){
                float a = s_xbg[k0+kk];
                float4 w = *(const float4*)&Wb[kk*DD];
                a0 = fmaf(a, w.x, a0); a1 = fmaf(a, w.y, a1);
                a2 = fmaf(a, w.z, a2); a3 = fmaf(a, w.w, a3);
            }
            float4 o; o.x=a0; o.y=a1; o.z=a2; o.w=a3;
            *(float4*)&part[m*1024 + ko*128 + j4] = o;
        } else if (bid < 12){
            int t = tid - 768;
            int cg = t & 31, ko = t >> 5;
            int k0 = ko*16, j4 = cg*4;
            int unit = bid;
            const float* W;
            if (unit < 3)       W = Wk;
            else if (unit < 6)  W = Wv;
            else if (unit == 6 || unit == 9)  W = Wq;
            else if (unit == 7 || unit == 10) W = Wk;
            else                W = Wv;
            const float* Wb = W + k0*DD + j4;
            float a0=0.f, a1=0.f, a2=0.f, a3=0.f;
            #pragma unroll
            for (int kk = 0; kk < 16; kk++){
                float a = s_aux[k0+kk];
                float4 w = *(const float4*)&Wb[kk*DD];
                a0 = fmaf(a, w.x, a0); a1 = fmaf(a, w.y, a1);
                a2 = fmaf(a, w.z, a2); a3 = fmaf(a, w.w, a3);
            }
            float4 o; o.x=a0; o.y=a1; o.z=a2; o.w=a3;
            *(float4*)&paux[ko*128 + j4] = o;
        } else if (bid == 12 && tid >= 768){
            // G = Wp Wp^T (9), rs (3)
            int w = (tid - 768) >> 5;
            for (int o = w; o < 12; o += 8){
                float acc = 0.0f;
                if (o < 9){
                    int a = o/3, c = o%3;
                    #pragma unroll
                    for (int q4 = 0; q4 < 4; q4++){
                        int k = lane + q4*32;
                        acc = fmaf(Wp[a*DD+k], Wp[c*DD+k], acc);
                    }
                    acc = warpSum(acc);
                    if (lane == 0) g_G[o] = acc;
                } else {
                    int a = o - 9;
                    #pragma unroll
                    for (int q4 = 0; q4 < 4; q4++) acc += Wp[a*DD + lane + q4*32];
                    acc = warpSum(acc);
                    if (lane == 0) g_rs[a] = acc;
                }
            }
        }
        __syncthreads();

        if (tid < 384){
            int m = tid >> 7, j = tid & 127;
            const float* pm = part + m*1024;
            float v = pm[j] + pm[128+j] + pm[256+j] + pm[384+j]
                    + pm[512+j] + pm[640+j] + pm[768+j] + pm[896+j];
            if      (m == 0) s_Xq[j] = v;
            else if (m == 1) g_Xk[bid*DD + j] = v;
            else             g_Xv[bid*DD + j] = v;
        } else if (bid < 12 && tid >= 384 && tid < 512){
            int j = tid - 384;
            int unit = bid;
            float* O; const float* bias = 0;
            if (unit < 3)      O = g_Mk + unit*DD;
            else if (unit < 6) O = g_Mv + (unit-3)*DD;
            else if (unit == 6) O = g_uq;
            else if (unit == 7) O = g_uk;
            else if (unit == 8) O = g_uv;
            else if (unit == 9){ O = g_cq; bias = bq; }
            else if (unit ==10){ O = g_ck; bias = bk; }
            else               { O = g_cv; bias = bv; }
            float v = paux[j] + paux[128+j] + paux[256+j] + paux[384+j]
                    + paux[512+j] + paux[640+j] + paux[768+j] + paux[896+j];
            O[j] = v + (bias ? bias[j] : 0.0f);
        }
    }

    // ===================== GLOBAL BARRIER (ticket + volatile spin) ============
    __syncthreads();
    if (tid == 0){
        __threadfence();
        unsigned my = atomicAdd(&g_tick, 1u);
        unsigned target = (my / GRID + 1u) * GRID;
        volatile unsigned* vt = &g_tick;
        while (*vt < target) { }
        __threadfence();
    }
    __syncthreads();

    // ===================== PHASE 2: attention (factored) =====================
    const float* cb = coords + b*LL*3;
    {
        float* s_q = s_buf;   // temp overlay until scores are written

        if (tid < 32){
            mk[tid]     = mask[b*32 + tid];
            s_mxb[tid]  = g_mxb[b*32 + tid];
            s_ssxb[tid] = g_ssxb[b*32 + tid];
        }
        if (tid >= 416 && tid < 512){
            int t = tid - 416;
            s_XW[t/3][t%3] = g_XW[b*96 + t];
        }
        if (tid >= 128 && tid < 256){
            int d = tid - 128;
            float mu_i = g_mxb[bid];
            float rstd_i = rsqrtf(g_ssxb[bid]*(1.0f/128.0f) - mu_i*mu_i + 1e-5f);
            s_q[d] = rstd_i*s_Xq[d] - rstd_i*mu_i*g_uq[d] + g_cq[d];
        }
        __syncthreads();

        if (tid < 256){
            int h = tid >> 5, n = tid & 31;
            const float4* q4 = (const float4*)&s_q[h*16];
            const float4* k4 = (const float4*)&g_Xk[(b*32+n)*DD + h*16];
            float acc = 0.0f;
            #pragma unroll
            for (int j = 0; j < 4; j++){
                float4 qq = q4[j], kk = k4[j];
                acc = fmaf(qq.x, kk.x, fmaf(qq.y, kk.y,
                      fmaf(qq.z, kk.z, fmaf(qq.w, kk.w, acc))));
            }
            s_QXk[h][n] = acc;
        } else if (tid < 280){
            int t = tid - 256;
            int h = t/3, a = t%3;
            float acc = 0.0f;
            #pragma unroll
            for (int j = 0; j < 16; j++) acc = fmaf(s_q[h*16+j], g_Mk[a*DD + h*16 + j], acc);
            s_qMk[h][a] = acc;
        } else if (tid < 288){
            int h = tid - 280;
            float acc = 0.0f;
            #pragma unroll
            for (int j = 0; j < 16; j++) acc = fmaf(s_q[h*16+j], g_uk[h*16+j], acc);
            s_quk[h] = acc;
        } else if (tid < 296){
            int h = tid - 288;
            float acc = 0.0f;
            #pragma unroll
            for (int j = 0; j < 16; j++) acc = fmaf(s_q[h*16+j], g_ck[h*16+j], acc);
            s_qck[h] = acc;
        }
        __syncthreads();
    }

    // scores + LN stats + coord-delta cache: one key per thread
    if (tid < LL){
        int l = tid;
        int c = l >> 5, n = l & 31;
        int lb = l*3, ib = (c*32 + i)*3;
        float d0 = cb[lb]   - cb[ib];
        float d1 = cb[lb+1] - cb[ib+1];
        float d2 = cb[lb+2] - cb[ib+2];
        s_dc0[l] = d0; s_dc1[l] = d1; s_dc2[l] = d2;
        float mu = s_mxb[n] + (d0*g_rs[0] + d1*g_rs[1] + d2*g_rs[2]) * (1.0f/128.0f);
        float ss = s_ssxb[n]
                 + 2.0f*(d0*s_XW[n][0] + d1*s_XW[n][1] + d2*s_XW[n][2])
                 + d0*(g_G[0]*d0 + g_G[1]*d1 + g_G[2]*d2)
                 + d1*(g_G[3]*d0 + g_G[4]*d1 + g_G[5]*d2)
                 + d2*(g_G[6]*d0 + g_G[7]*d1 + g_G[8]*d2);
        float var = ss*(1.0f/128.0f) - mu*mu;
        float rstd = rsqrtf(var + 1e-5f);
        s_mu[l] = mu; s_rstd[l] = rstd;
        float rm = rstd*mu;
        bool msk = (mk[n] == 0);
        #pragma unroll
        for (int h = 0; h < 8; h++){
            float s = rstd*(s_QXk[h][n] + d0*s_qMk[h][0] + d1*s_qMk[h][1] + d2*s_qMk[h][2])
                    - rm*s_quk[h] + s_qck[h];
            s *= 0.25f;
            s_buf[h*LL + l] = msk ? -1e9f : s;
        }
    }
    __syncthreads();

    // softmax: 4 warps per head, online merge; scale folded into V pass
    {
        int w = tid >> 5;
        int h = w & 7, q = w >> 3;
        int start = q*32 + lane;
        float* sch = s_buf + h*LL;
        float m = -3.4e38f;
        for (int l = start; l < LL; l += 128) m = fmaxf(m, sch[l]);
        #pragma unroll
        for (int o = 16; o; o >>= 1) m = fmaxf(m, __shfl_xor_sync(0xffffffffu, m, o));
        float sum = 0.0f;
        for (int l = start; l < LL; l += 128){
            float e = __expf(sch[l] - m);
            sch[l] = e;
            sum += e;
        }
        #pragma unroll
        for (int o = 16; o; o >>= 1) sum += __shfl_xor_sync(0xffffffffu, sum, o);
        if (lane == 0){ s_sm4[q][h][0] = m; s_sm4[q][h][1] = sum; }
        __syncthreads();
        if (lane == 0){
            float m0 = s_sm4[0][h][0], m1 = s_sm4[1][h][0];
            float m2 = s_sm4[2][h][0], m3 = s_sm4[3][h][0];
            float M = fmaxf(fmaxf(m0, m1), fmaxf(m2, m3));
            float S = s_sm4[0][h][1]*__expf(m0 - M) + s_sm4[1][h][1]*__expf(m1 - M)
                    + s_sm4[2][h][1]*__expf(m2 - M) + s_sm4[3][h][1]*__expf(m3 - M);
            s_scaleq[q][h] = __expf(s_sm4[q][h][0] - M) / S;
        }
    }
    __syncthreads();

    // V aggregates: 32 warps = (c-quarter, head); all smem, scale folded in.
    // element l=c*32+n was normalized by softmax-warp quarter (c & 3).
    {
        int w = tid >> 5, n = lane;
        int h = w & 7, q = w >> 3;
        int c0 = q*7, c1 = (q == 3) ? 27 : c0 + 7;
        const float* sch = s_buf + h*LL;
        float A = 0.f, B0 = 0.f, B1 = 0.f, B2 = 0.f, Gp = 0.f;
        #pragma unroll 1
        for (int c = c0; c < c1; c++){
            int l = c*32 + n;
            float scl = s_scaleq[c & 3][h];
            float wr = sch[l] * scl * s_rstd[l];
            A += wr;
            B0 = fmaf(wr, s_dc0[l], B0);
            B1 = fmaf(wr, s_dc1[l], B1);
            B2 = fmaf(wr, s_dc2[l], B2);
            Gp = fmaf(-wr, s_mu[l], Gp);
        }
        s_Ap[q][h][n] = A;
        B0 = warpSum(B0); B1 = warpSum(B1); B2 = warpSum(B2); Gp = warpSum(Gp);
        if (n == 0){
            s_Bp[q][h][0]=B0; s_Bp[q][h][1]=B1; s_Bp[q][h][2]=B2; s_Gp4[q][h]=Gp;
        }
    }
    __syncthreads();
    if (tid < 256){
        int h = tid >> 5, n = tid & 31;
        s_A[h][n] = s_Ap[0][h][n] + s_Ap[1][h][n] + s_Ap[2][h][n] + s_Ap[3][h][n];
    } else if (tid < 280){
        int t = tid - 256;
        int h = t/3, a = t%3;
        s_B[h][a] = s_Bp[0][h][a] + s_Bp[1][h][a] + s_Bp[2][h][a] + s_Bp[3][h][a];
    } else if (tid < 288){
        int h = tid - 280;
        s_G8[h] = s_Gp4[0][h] + s_Gp4[1][h] + s_Gp4[2][h] + s_Gp4[3][h];
    }
    __syncthreads();

    // atts: n-split 8 (4-iter chains), then Wo (float4, 32-way k-split)
    {
        float* pa = s_buf;             // 1024 partials

        {
            int d = tid & 127, nh = tid >> 7;
            int h = d >> 4;
            float acc;
            if (nh == 0){
                acc = g_cv[d] + s_G8[h]*g_uv[d]
                    + s_B[h][0]*g_Mv[d] + s_B[h][1]*g_Mv[DD+d] + s_B[h][2]*g_Mv[2*DD+d];
            } else acc = 0.0f;
            const float* Xvb = g_Xv + b*32*DD;
            int n0 = nh*4;
            #pragma unroll
            for (int n = 0; n < 4; n++) acc = fmaf(s_A[h][n0+n], Xvb[(n0+n)*DD + d], acc);
            pa[nh*128 + d] = acc;
        }
        __syncthreads();
        if (tid < 128)
            s_atts[tid] = pa[tid] + pa[128+tid] + pa[256+tid] + pa[384+tid]
                        + pa[512+tid] + pa[640+tid] + pa[768+tid] + pa[896+tid];
        __syncthreads();

        // Wo: 32 col-quads x 32 k-splits (4 k each), float4 loads
        float* red  = s_buf;           // 4096
        float* red2 = s_buf + 4096;    // 512
        {
            int cg = tid & 31, ks = tid >> 5;
            int k0 = ks*4, j4 = cg*4;
            const float* Wb = Wo + k0*DD + j4;
            float a0=0.f, a1=0.f, a2=0.f, a3=0.f;
            #pragma unroll
            for (int kk = 0; kk < 4; kk++){
                float a = s_atts[k0+kk];
                float4 w = *(const float4*)&Wb[kk*DD];
                a0 = fmaf(a, w.x, a0); a1 = fmaf(a, w.y, a1);
                a2 = fmaf(a, w.z, a2); a3 = fmaf(a, w.w, a3);
            }
            float4 o; o.x=a0; o.y=a1; o.z=a2; o.w=a3;
            *(float4*)&red[ks*128 + j4] = o;
        }
        __syncthreads();
        if (tid < 512){
            int j = tid & 127, g = tid >> 7;
            float v = 0.0f;
            #pragma unroll
            for (int t = 0; t < 8; t++) v += red[(g + 4*t)*128 + j];
            red2[g*128 + j] = v;
        }
        __syncthreads();
        if (tid < 128){
            float y = s_xb[tid] + bo[tid]
                    + red2[tid] + red2[128+tid] + red2[256+tid] + red2[384+tid];
            s_yrow[tid] = y;
            float s = warpSum(y), s2 = warpSum(y*y);
            if (lane == 0){ rsm[tid>>5][0] = s; rsm[tid>>5][1] = s2; }
        }
        __syncthreads();
        if (tid == 0){
            float s  = rsm[0][0]+rsm[1][0]+rsm[2][0]+rsm[3][0];
            float s2 = rsm[0][1]+rsm[1][1]+rsm[2][1]+rsm[3][1];
            float m = s * (1.0f/128.0f);
            stat[0] = m;
            stat[1] = rsqrtf(s2*(1.0f/128.0f) - m*m + 1e-5f);
        }
        __syncthreads();
        if (tid < 128)
            s_hn2[tid] = (s_yrow[tid] - stat[0])*stat[1]*g2[tid] + b2[tid];
        __syncthreads();
    }

    // ===================== PHASE 3: FFN (float4, full-MLP unrolls) ============
    {
        float* zp = s_buf;             // 8*512 = 4096 partials
        float* zs = s_buf + 4096;      // 512

        // stage 1: 128 col-quads x 8 k-octants, full unroll
        {
            int cg = tid & 127, ko = tid >> 7;
            int k0 = ko*16, j4 = cg*4;
            const float* Wb = W1 + k0*DFF + j4;
            float a0=0.f, a1=0.f, a2=0.f, a3=0.f;
            #pragma unroll
            for (int kk = 0; kk < 16; kk++){
                float a = s_hn2[k0+kk];
                float4 w = *(const float4*)&Wb[kk*DFF];
                a0 = fmaf(a, w.x, a0); a1 = fmaf(a, w.y, a1);
                a2 = fmaf(a, w.z, a2); a3 = fmaf(a, w.w, a3);
            }
            float4 o; o.x=a0; o.y=a1; o.z=a2; o.w=a3;
            *(float4*)&zp[ko*512 + j4] = o;
        }
        __syncthreads();
        if (tid < 512){
            float v = zp[tid] + zp[512+tid] + zp[1024+tid] + zp[1536+tid]
                    + zp[2048+tid] + zp[2560+tid] + zp[3072+tid] + zp[3584+tid];
            zs[tid] = fmaxf(v + bf1[tid], 0.0f);
        }
        __syncthreads();

        // stage 2: 32 col-quads x 32 k-splits (16 k each), full unroll
        float* red  = s_buf;           // 4096 (zp region reused)
        float* red2 = s_buf + 4608;    // 512
        {
            int cg = tid & 31, ks = tid >> 5;
            int k0 = ks*16, j4 = cg*4;
            const float* Wb = W2 + k0*DD + j4;
            float a0=0.f, a1=0.f, a2=0.f, a3=0.f;
            #pragma unroll
            for (int kk = 0; kk < 16; kk++){
                float a = zs[k0+kk];
                float4 w = *(const float4*)&Wb[kk*DD];
                a0 = fmaf(a, w.x, a0); a1 = fmaf(a, w.y, a1);
                a2 = fmaf(a, w.z, a2); a3 = fmaf(a, w.w, a3);
            }
            float4 o; o.x=a0; o.y=a1; o.z=a2; o.w=a3;
            *(float4*)&red[ks*128 + j4] = o;
        }
        __syncthreads();
        if (tid < 512){
            int j = tid & 127, g = tid >> 7;
            float v = 0.0f;
            #pragma unroll
            for (int t = 0; t < 8; t++) v += red[(g + 4*t)*128 + j];
            red2[g*128 + j] = v;
        }
        __syncthreads();
        if (tid < 128)
            out[bid*DD + tid] = s_yrow[tid] + bf2[tid]
                              + red2[tid] + red2[128+tid] + red2[256+tid] + red2[384+tid];
    }
}

// ---------------- launch ------------------------------------------------------
extern "C" void kernel_launch(void* const* d_in, const int* in_sizes, int n_in,
                              void* d_out, int out_size)
{
    const float* x      = (const float*)d_in[0];
    const int*   mask   = (const int*)  d_in[1];
    const float* coords = (const float*)d_in[2];
    const float* Wp = (const float*)d_in[3],  *bp  = (const float*)d_in[4];
    const float* Wq = (const float*)d_in[5],  *bq  = (const float*)d_in[6];
    const float* Wk = (const float*)d_in[7],  *bk  = (const float*)d_in[8];
    const float* Wv = (const float*)d_in[9],  *bv  = (const float*)d_in[10];
    const float* Wo = (const float*)d_in[11], *bo  = (const float*)d_in[12];
    const float* g1 = (const float*)d_in[13], *b1  = (const float*)d_in[14];
    const float* g2 = (const float*)d_in[15], *b2  = (const float*)d_in[16];
    const float* W1 = (const float*)d_in[17], *bf1 = (const float*)d_in[18];
    const float* W2 = (const float*)d_in[19], *bf2 = (const float*)d_in[20];
    float* out = (float*)d_out;

    k_fused<<<GRID, TPB>>>(x, mask, coords, Wp, bp, Wq, bq, Wk, bk, Wv, bv,
                           Wo, bo, g1, b1, g2, b2, W1, bf1, W2, bf2, out);
}